// round 11
// baseline (speedup 1.0000x reference)
#include <cuda_runtime.h>
#include <cuda_fp16.h>
#include <cstdint>

#define SEQ 512
#define BS 64
#define IN_DIM 1024
#define HDIM 1024
#define G4 4096           // 4 gates * H, packed as [k][j*4 + gate]
#define KD 1024
#define NCTA 128
#define NTHR 256

// ---------------- device scratch (allocation rules forbid cudaMalloc) -----------
__device__ __half g_Wx0h[(size_t)G4 * KD];        // layer0 input W, [n][kperm] fp16
__device__ __half g_Wx1h[(size_t)G4 * KD];        // layer1 input W, [n][kperm] fp16
__device__ __half g_Whh [(size_t)G4 * KD];        // recurrent W,   [n][kperm] fp16
__device__ float  g_bias[G4];
__device__ float  g_xw [(size_t)SEQ * BS * G4];   // X@Wx0 + b (layer 0)
__device__ __half g_Ah [(size_t)SEQ * BS * KD];   // GEMM A, fp16 [m][kperm]
__device__ __half g_h0A[BS * HDIM];               // layer0 h ring-of-3 (fp16 perm)
__device__ __half g_h0B[BS * HDIM];
__device__ __half g_h0C[BS * HDIM];
__device__ __half g_h1A[BS * HDIM];               // layer1 h ring-of-2 (fp16 perm)
__device__ __half g_h1B[BS * HDIM];
__device__ float  g_c [BS * HDIM];

// monotonic per-CTA step flags (graph-replay safe: base re-read each launch)
__device__ __align__(16) unsigned g_flags[NCTA];

// ---------------- helpers -------------------------------------------------------
__device__ __forceinline__ void mma_f16(float& c0, float& c1, float& c2, float& c3,
                                        unsigned a0, unsigned a1, unsigned a2, unsigned a3,
                                        unsigned b0, unsigned b1) {
    asm volatile(
        "mma.sync.aligned.m16n8k16.row.col.f32.f16.f16.f32 "
        "{%0,%1,%2,%3}, {%4,%5,%6,%7}, {%8,%9}, {%0,%1,%2,%3};"
        : "+f"(c0), "+f"(c1), "+f"(c2), "+f"(c3)
        : "r"(a0), "r"(a1), "r"(a2), "r"(a3), "r"(b0), "r"(b1));
}

__device__ __forceinline__ float sigmoidf_(float x) {
    return 1.0f / (1.0f + __expf(-x));
}
__device__ __forceinline__ float tanhfast(float x) {
    float y; asm("tanh.approx.f32 %0, %1;" : "=f"(y) : "f"(x)); return y;
}

__device__ __forceinline__ void st_rel(unsigned* p, unsigned v) {
    asm volatile("st.release.gpu.global.u32 [%0], %1;" :: "l"(p), "r"(v) : "memory");
}
__device__ __forceinline__ uint4 ldv4_vol(const unsigned* p) {
    uint4 v;
    asm volatile("ld.volatile.global.v4.u32 {%0,%1,%2,%3}, [%4];"
                 : "=r"(v.x), "=r"(v.y), "=r"(v.z), "=r"(v.w) : "l"(p) : "memory");
    return v;
}

__device__ __forceinline__ void cpa16(void* s, const void* g) {
    unsigned sa = (unsigned)__cvta_generic_to_shared(s);
    asm volatile("cp.async.cg.shared.global [%0], [%1], 16;" :: "r"(sa), "l"(g));
}
__device__ __forceinline__ void cpa_commit() {
    asm volatile("cp.async.commit_group;");
}
__device__ __forceinline__ void cpa_wait1() {
    asm volatile("cp.async.wait_group 1;");
}

// fp16 k-permutation within each 32-k block
__device__ __host__ __forceinline__ int hperm16(int k) {
    int t = k & 31;
    int tile = t >> 4;
    int u = t & 15;
    int b = u & 1;
    int tg = (u >> 1) & 3;
    int c = u >> 3;
    return (k & ~31) | (tg * 8 + tile * 4 + c * 2 + b);
}

// ---------------- fused packing kernel --------------------------------------------
__global__ void pack_all(
    const float* __restrict__ Wi0, const float* __restrict__ Wf0,
    const float* __restrict__ Wg0, const float* __restrict__ Wo0,
    const float* __restrict__ Wi1, const float* __restrict__ Wf1,
    const float* __restrict__ Wg1, const float* __restrict__ Wo1,
    const float* __restrict__ Whi, const float* __restrict__ Whf,
    const float* __restrict__ Whg, const float* __restrict__ Who,
    const float* __restrict__ bi,  const float* __restrict__ bf,
    const float* __restrict__ bg,  const float* __restrict__ bo,
    __half* __restrict__ Wx0h, __half* __restrict__ Wx1h,
    __half* __restrict__ Whh, float* __restrict__ bias) {
    const int bid = blockIdx.x;
    const int tid = threadIdx.x;
    if (bid < 3072) {
        const int set = bid >> 10;
        const int rem = bid & 1023;
        const int gate = rem >> 8;
        const int tile = rem & 255;
        const float* W;
        __half* dst;
        if (set == 0) {
            W = (gate == 0) ? Wi0 : (gate == 1) ? Wf0 : (gate == 2) ? Wg0 : Wo0;
            dst = Wx0h;
        } else if (set == 1) {
            W = (gate == 0) ? Wi1 : (gate == 1) ? Wf1 : (gate == 2) ? Wg1 : Wo1;
            dst = Wx1h;
        } else {
            W = (gate == 0) ? Whi : (gate == 1) ? Whf : (gate == 2) ? Whg : Who;
            dst = Whh;
        }
        const int k0 = (tile & 15) * 64, j0 = (tile >> 4) * 64;
        __shared__ __half t[64][65];
#pragma unroll
        for (int it = 0; it < 16; it++) {
            int v = tid + it * 256;
            int ky = v >> 6, jx = v & 63;
            t[ky][jx] = __float2half(W[(size_t)(k0 + ky) * HDIM + j0 + jx]);
        }
        __syncthreads();
#pragma unroll
        for (int it = 0; it < 16; it++) {
            int v = tid + it * 256;
            int jy = v >> 6, kx = v & 63;
            int n = (j0 + jy) * 4 + gate;
            dst[(size_t)n * KD + hperm16(k0 + kx)] = t[kx][jy];
        }
    } else {
#pragma unroll
        for (int e = 0; e < 4; e++) {
            int j = tid + e * 256;
            float4 v;
            v.x = bi[j]; v.y = bf[j]; v.z = bg[j]; v.w = bo[j];
            reinterpret_cast<float4*>(bias)[j] = v;
        }
    }
}

// A conversion: fp32 [m][k] -> fp16 [m][hperm16(k)]
__global__ void cvtA(const float* __restrict__ src, __half* __restrict__ dst, int total) {
    int i2 = blockIdx.x * blockDim.x + threadIdx.x;
    int idx = i2 * 2;
    if (idx >= total) return;
    float2 v = *reinterpret_cast<const float2*>(src + idx);
    int m = idx >> 10, k = idx & 1023;
    *reinterpret_cast<__half2*>(dst + ((size_t)m << 10) + hperm16(k)) =
        __floats2half2_rn(v.x, v.y);
}

// ---------------- big input-projection GEMM (fp16, cp.async 2-stage) -------------
#define GSTR 96
#define GSTAGE (128 * GSTR)

__global__ void __launch_bounds__(256, 2)
gemm_xw_f16(const __half* __restrict__ A, const __half* __restrict__ B,
            float* __restrict__ C, const float* __restrict__ bias) {
    extern __shared__ __align__(16) __half gs[];
    const int m0 = blockIdx.y * 128;
    const int n0 = blockIdx.x * 128;
    const int tid  = threadIdx.x;
    const int warp = tid >> 5, lane = tid & 31;
    const int grp  = lane >> 2, tg = lane & 3;
    const int wm = warp & 1;
    const int wn = warp >> 1;

    const int cc = tid & 7;
    const int rr = tid >> 3;

    auto issue = [&](int st, int kofs) {
        __half* As = gs + st * GSTAGE;
        __half* Bs = gs + 2 * GSTAGE + st * GSTAGE;
#pragma unroll
        for (int i = 0; i < 4; i++) {
            int row = rr + i * 32;
            cpa16(As + row * GSTR + cc * 8,
                  A + (size_t)(m0 + row) * KD + kofs + cc * 8);
            cpa16(Bs + row * GSTR + cc * 8,
                  B + (size_t)(n0 + row) * KD + kofs + cc * 8);
        }
        cpa_commit();
    };

    issue(0, 0);
    issue(1, 64);

    float acc[4][4][4];
#pragma unroll
    for (int mi = 0; mi < 4; mi++)
#pragma unroll
        for (int ni = 0; ni < 4; ni++)
#pragma unroll
            for (int q = 0; q < 4; q++) acc[mi][ni][q] = 0.0f;

    for (int kt = 0; kt < 16; kt++) {
        cpa_wait1();
        __syncthreads();
        const __half* As = gs + (kt & 1) * GSTAGE;
        const __half* Bs = gs + 2 * GSTAGE + (kt & 1) * GSTAGE;

#pragma unroll
        for (int g32 = 0; g32 < 2; g32++) {
            const int ko = g32 * 32 + tg * 8;
            uint4 Bf[4];
#pragma unroll
            for (int ni = 0; ni < 4; ni++) {
                const int c = wn * 32 + ni * 8 + grp;
                Bf[ni] = *reinterpret_cast<const uint4*>(Bs + c * GSTR + ko);
            }
#pragma unroll
            for (int mi = 0; mi < 4; mi++) {
                const int r = wm * 64 + mi * 16 + grp;
                uint4 Aa = *reinterpret_cast<const uint4*>(As + (r    ) * GSTR + ko);
                uint4 Ab = *reinterpret_cast<const uint4*>(As + (r + 8) * GSTR + ko);
#pragma unroll
                for (int ni = 0; ni < 4; ni++) {
                    mma_f16(acc[mi][ni][0], acc[mi][ni][1], acc[mi][ni][2], acc[mi][ni][3],
                            Aa.x, Ab.x, Aa.y, Ab.y, Bf[ni].x, Bf[ni].y);
                    mma_f16(acc[mi][ni][0], acc[mi][ni][1], acc[mi][ni][2], acc[mi][ni][3],
                            Aa.z, Ab.z, Aa.w, Ab.w, Bf[ni].z, Bf[ni].w);
                }
            }
        }
        __syncthreads();
        if (kt < 14) issue(kt & 1, (kt + 2) * 64);
        else cpa_commit();
    }

#pragma unroll
    for (int mi = 0; mi < 4; mi++) {
        const int r = m0 + wm * 64 + mi * 16 + grp;
#pragma unroll
        for (int ni = 0; ni < 4; ni++) {
            const int c = n0 + wn * 32 + ni * 8 + tg * 2;
            float2 bv = *reinterpret_cast<const float2*>(bias + c);
            float2 o0, o1;
            o0.x = acc[mi][ni][0] + bv.x;  o0.y = acc[mi][ni][1] + bv.y;
            o1.x = acc[mi][ni][2] + bv.x;  o1.y = acc[mi][ni][3] + bv.y;
            *reinterpret_cast<float2*>(C + (size_t)r * G4 + c)       = o0;
            *reinterpret_cast<float2*>(C + (size_t)(r + 8) * G4 + c) = o1;
        }
    }
}
#define GEMM_SMEM (4 * GSTAGE * (int)sizeof(__half))   // 96 KB

// ---------------- fused two-layer persistent recurrence (Y-ring merged phase) -----
// Round s (0..513):
//   PRE-WAIT : rc = carry partials (h0(s-2)@Wx1 from round s-1); xw(s) prefetch
//   WAIT(s)  : warp-0-only vectorized flag poll
//   MERGED   : X = h0(s-1) depth-1 stream; Y = h1(s-3) register ring-4 (burst
//              issued 4 groups ahead). Per group: acc1 (Y@Wh) first, then
//              acc0 (X@Wh) and accC (X@Wx1). Spill acc0/acc1 fp32, accC fp16.
//   EPILOGUE : h0(s), h1(s-2) stores -> flag -> deferred seq/cdump stores
#define WT_STRIDE 1056              // halves
#define PS_STRIDE 36                // floats (Ps0/Ps1), halves (PsC)
#define WSLICE (32 * WT_STRIDE)     // halves per weight slice
#define PSLICE (4 * 64 * PS_STRIDE) // floats per fp32 partial buffer
#define SMEM_BYTES (2 * WSLICE * 2 + 2 * PSLICE * 4 + PSLICE * 2)   // 222 KB

__global__ void __launch_bounds__(NTHR, 1)
lstm_fused(const float* __restrict__ xw,
           __half* __restrict__ h0A, __half* __restrict__ h0B, __half* __restrict__ h0C,
           __half* __restrict__ h1A, __half* __restrict__ h1B,
           float* __restrict__ cdump, float* __restrict__ seq_out) {
    extern __shared__ __align__(16) unsigned char smem_raw[];
    __half* WhS  = reinterpret_cast<__half*>(smem_raw);              // [32][WT_STRIDE]
    __half* Wx1S = WhS + WSLICE;                                     // [32][WT_STRIDE]
    float*  Ps0  = reinterpret_cast<float*>(smem_raw + 2 * WSLICE * 2);
    float*  Ps1  = Ps0 + PSLICE;
    __half* PsC  = reinterpret_cast<__half*>(Ps1 + PSLICE);          // fp16 carry

    const int tid  = threadIdx.x;
    const int warp = tid >> 5, lane = tid & 31;
    const int grp  = lane >> 2, tg = lane & 3;
    const int wm = warp & 1;                 // M half (32 rows)
    const int ks = warp >> 1;                // K slice: [ks*256, +256)

    const int n0 = blockIdx.x * 32;          // packed gate column base
    const int J0 = blockIdx.x * 8;           // hidden-unit base

    const unsigned base = g_flags[blockIdx.x];

    // ---- preload weight slices ([n][kperm] fp16: raw vector copies) ----
    for (int idx = tid; idx < 32 * 128; idx += NTHR) {
        int c = idx >> 7, ch = idx & 127;
        *reinterpret_cast<uint4*>(WhS  + c * WT_STRIDE + ch * 8) =
            *reinterpret_cast<const uint4*>(g_Whh  + (size_t)(n0 + c) * KD + ch * 8);
        *reinterpret_cast<uint4*>(Wx1S + c * WT_STRIDE + ch * 8) =
            *reinterpret_cast<const uint4*>(g_Wx1h + (size_t)(n0 + c) * KD + ch * 8);
    }

    // ---- zero own h columns (all 5 buffers) + PsC ----
    for (int idx = tid; idx < 512; idx += NTHR) {
        int b = idx >> 3, j = idx & 7;
        int p = b * HDIM + hperm16(J0 + j);
        __half z = __float2half(0.0f);
        h0A[p] = z; h0B[p] = z; h0C[p] = z; h1A[p] = z; h1B[p] = z;
    }
    for (int idx = tid; idx < PSLICE / 2; idx += NTHR)
        reinterpret_cast<uint*>(PsC)[idx] = 0u;

    // ---- per-thread layer-1 bias ----
    float4 bs1[2];
#pragma unroll
    for (int it = 0; it < 2; it++) {
        int idx = tid + it * NTHR;
        int col = (idx & 7) << 2;
        bs1[it] = *reinterpret_cast<const float4*>(g_bias + n0 + col);
    }

    __syncthreads();
    if (tid == 0) st_rel(&g_flags[blockIdx.x], base + 1);

    float c0reg[2] = {0.0f, 0.0f};
    float c1reg[2] = {0.0f, 0.0f};
    __half* h0buf[3] = {h0A, h0B, h0C};
    __half* h1buf[2] = {h1A, h1B};

    const int r0 = wm * 32 + grp;
    const int kbase = ks * 256;
    const size_t laneoff = kbase + tg * 8;

    for (int s = 0; s <= SEQ + 1; s++) {
        // ---- PRE-WAIT: carry rc = h0(s-2)@Wx1 partials (own SMEM) ----
        float4 rc[2];
#pragma unroll
        for (int it = 0; it < 2; it++) {
            int idx = tid + it * NTHR;
            int b = idx >> 3, j = idx & 7;
            const __half* cb = PsC + b * PS_STRIDE + (j << 2);
            float4 rs = make_float4(0.f, 0.f, 0.f, 0.f);
#pragma unroll
            for (int k4 = 0; k4 < 4; k4++) {
                uint2 raw = *reinterpret_cast<const uint2*>(cb + k4 * 64 * PS_STRIDE);
                float2 f0 = __half22float2(*reinterpret_cast<__half2*>(&raw.x));
                float2 f1 = __half22float2(*reinterpret_cast<__half2*>(&raw.y));
                rs.x += f0.x; rs.y += f0.y; rs.z += f1.x; rs.w += f1.y;
            }
            rc[it] = rs;
        }

        // ---- prefetch xw(s) ----
        float4 xv[2];
        if (s < SEQ) {
            const float* xw_t = xw + (size_t)s * BS * G4;
#pragma unroll
            for (int it = 0; it < 2; it++) {
                int idx = tid + it * NTHR;
                int b = idx >> 3, col = (idx & 7) << 2;
                xv[it] = *reinterpret_cast<const float4*>(xw_t + (size_t)b * G4 + n0 + col);
            }
        }

        // ---- WAIT: warp 0 polls all 128 flags (4/lane, vectorized) ----
        {
            const unsigned target = base + 1 + (unsigned)s;
            if (warp == 0) {
                const unsigned* fp = g_flags + lane * 4;
                bool ok;
                do {
                    uint4 v = ldv4_vol(fp);
                    ok = ((int)(v.x - target) >= 0) && ((int)(v.y - target) >= 0) &&
                         ((int)(v.z - target) >= 0) && ((int)(v.w - target) >= 0);
                } while (!__all_sync(0xffffffffu, ok));
                asm volatile("fence.acq_rel.gpu;" ::: "memory");
            }
            __syncthreads();
        }

        // ---- MERGED phase: X = h0(s-1) depth-1; Y = h1(s-3) ring-4 ----
        {
            const __half* xr = h0buf[(s + 2) % 3];
            const __half* yr = h1buf[(s + 1) & 1];
            const __half* xp0 = xr + (size_t)(r0      ) * KD + laneoff;
            const __half* xp1 = xr + (size_t)(r0 +  8) * KD + laneoff;
            const __half* xp2 = xr + (size_t)(r0 + 16) * KD + laneoff;
            const __half* xp3 = xr + (size_t)(r0 + 24) * KD + laneoff;
            const __half* yp0 = yr + (size_t)(r0      ) * KD + laneoff;
            const __half* yp1 = yr + (size_t)(r0 +  8) * KD + laneoff;
            const __half* yp2 = yr + (size_t)(r0 + 16) * KD + laneoff;
            const __half* yp3 = yr + (size_t)(r0 + 24) * KD + laneoff;

            float acc0[2][4][4], acc1[2][4][4], accC[2][4][4];
#pragma unroll
            for (int mt = 0; mt < 2; mt++)
#pragma unroll
                for (int nt = 0; nt < 4; nt++)
#pragma unroll
                    for (int q = 0; q < 4; q++) {
                        acc0[mt][nt][q] = 0.0f; acc1[mt][nt][q] = 0.0f; accC[mt][nt][q] = 0.0f;
                    }

            // Y register ring: 4 groups in flight
            uint4 Yr[4][4];
#pragma unroll
            for (int q = 0; q < 4; q++) {
                const int off = q * 32;
                Yr[q][0] = *reinterpret_cast<const uint4*>(yp0 + off);
                Yr[q][1] = *reinterpret_cast<const uint4*>(yp1 + off);
                Yr[q][2] = *reinterpret_cast<const uint4*>(yp2 + off);
                Yr[q][3] = *reinterpret_cast<const uint4*>(yp3 + off);
            }
            uint4 X0 = *reinterpret_cast<const uint4*>(xp0);
            uint4 X1 = *reinterpret_cast<const uint4*>(xp1);
            uint4 X2 = *reinterpret_cast<const uint4*>(xp2);
            uint4 X3 = *reinterpret_cast<const uint4*>(xp3);

#pragma unroll
            for (int g = 0; g < 8; g++) {
                const int slot = g & 3;
                uint4 NX0, NX1, NX2, NX3;
                if (g < 7) {
                    const int off = (g + 1) * 32;
                    NX0 = *reinterpret_cast<const uint4*>(xp0 + off);
                    NX1 = *reinterpret_cast<const uint4*>(xp1 + off);
                    NX2 = *reinterpret_cast<const uint4*>(xp2 + off);
                    NX3 = *reinterpret_cast<const uint4*>(xp3 + off);
                }
#pragma unroll
                for (int nt = 0; nt < 4; nt++) {
                    const int c = nt * 8 + grp;
                    uint4 Bv = *reinterpret_cast<const uint4*>(
                        WhS + c * WT_STRIDE + kbase + g * 32 + tg * 8);
                    uint4 Cv = *reinterpret_cast<const uint4*>(
                        Wx1S + c * WT_STRIDE + kbase + g * 32 + tg * 8);
                    // acc1 = Y @ Wh first (Y always resident)
                    mma_f16(acc1[0][nt][0], acc1[0][nt][1], acc1[0][nt][2], acc1[0][nt][3],
                            Yr[slot][0].x, Yr[slot][1].x, Yr[slot][0].y, Yr[slot][1].y, Bv.x, Bv.y);
                    mma_f16(acc1[1][nt][0], acc1[1][nt][1], acc1[1][nt][2], acc1[1][nt][3],
                            Yr[slot][2].x, Yr[slot][3].x, Yr[slot][2].y, Yr[slot][3].y, Bv.x, Bv.y);
                    mma_f16(acc1[0][nt][0], acc1[0][nt][1], acc1[0][nt][2], acc1[0][nt][3],
                            Yr[slot][0].z, Yr[slot][1].z, Yr[slot][0].w, Yr[slot][1].w, Bv.z, Bv.w);
                    mma_f16(acc1[1][nt][0], acc1[1][nt][1], acc1[1][nt][2], acc1[1][nt][3],
                            Yr[slot][2].z, Yr[slot][3].z, Yr[slot][2].w, Yr[slot][3].w, Bv.z, Bv.w);
                    // acc0 = X @ Wh
                    mma_f16(acc0[0][nt][0], acc0[0][nt][1], acc0[0][nt][2], acc0[0][nt][3],
                            X0.x, X1.x, X0.y, X1.y, Bv.x, Bv.y);
                    mma_f16(acc0[1][nt][0], acc0[1][nt][1], acc0[1][nt][2], acc0[1][nt][3],
                            X2.x, X3.x, X2.y, X3.y, Bv.x, Bv.y);
                    mma_f16(acc0[0][nt][0], acc0[0][nt][1], acc0[0][nt][2], acc0[0][nt][3],
                            X0.z, X1.z, X0.w, X1.w, Bv.z, Bv.w);
                    mma_f16(acc0[1][nt][0], acc0[1][nt][1], acc0[1][nt][2], acc0[1][nt][3],
                            X2.z, X3.z, X2.w, X3.w, Bv.z, Bv.w);
                    // accC = X @ Wx1
                    mma_f16(accC[0][nt][0], accC[0][nt][1], accC[0][nt][2], accC[0][nt][3],
                            X0.x, X1.x, X0.y, X1.y, Cv.x, Cv.y);
                    mma_f16(accC[1][nt][0], accC[1][nt][1], accC[1][nt][2], accC[1][nt][3],
                            X2.x, X3.x, X2.y, X3.y, Cv.x, Cv.y);
                    mma_f16(accC[0][nt][0], accC[0][nt][1], accC[0][nt][2], accC[0][nt][3],
                            X0.z, X1.z, X0.w, X1.w, Cv.z, Cv.w);
                    mma_f16(accC[1][nt][0], accC[1][nt][1], accC[1][nt][2], accC[1][nt][3],
                            X2.z, X3.z, X2.w, X3.w, Cv.z, Cv.w);
                }
                // refill Y ring slot with group g+4 (after last use of slot)
                if (g < 4) {
                    const int off = (g + 4) * 32;
                    Yr[slot][0] = *reinterpret_cast<const uint4*>(yp0 + off);
                    Yr[slot][1] = *reinterpret_cast<const uint4*>(yp1 + off);
                    Yr[slot][2] = *reinterpret_cast<const uint4*>(yp2 + off);
                    Yr[slot][3] = *reinterpret_cast<const uint4*>(yp3 + off);
                }
                X0 = NX0; X1 = NX1; X2 = NX2; X3 = NX3;
            }

            // spill: acc0/acc1 fp32, accC fp16 carry for round s+1
            float*  P0s = Ps0 + ks * 64 * PS_STRIDE;
            float*  P1s = Ps1 + ks * 64 * PS_STRIDE;
            __half* PCs = PsC + ks * 64 * PS_STRIDE;
#pragma unroll
            for (int mt = 0; mt < 2; mt++) {
                const int r = wm * 32 + mt * 16 + grp;
#pragma unroll
                for (int nt = 0; nt < 4; nt++) {
                    const int c = nt * 8 + tg * 2;
                    *reinterpret_cast<float2*>(P0s + (r    ) * PS_STRIDE + c) =
                        make_float2(acc0[mt][nt][0], acc0[mt][nt][1]);
                    *reinterpret_cast<float2*>(P0s + (r + 8) * PS_STRIDE + c) =
                        make_float2(acc0[mt][nt][2], acc0[mt][nt][3]);
                    *reinterpret_cast<float2*>(P1s + (r    ) * PS_STRIDE + c) =
                        make_float2(acc1[mt][nt][0], acc1[mt][nt][1]);
                    *reinterpret_cast<float2*>(P1s + (r + 8) * PS_STRIDE + c) =
                        make_float2(acc1[mt][nt][2], acc1[mt][nt][3]);
                    *reinterpret_cast<__half2*>(PCs + (r    ) * PS_STRIDE + c) =
                        __floats2half2_rn(accC[mt][nt][0], accC[mt][nt][1]);
                    *reinterpret_cast<__half2*>(PCs + (r + 8) * PS_STRIDE + c) =
                        __floats2half2_rn(accC[mt][nt][2], accC[mt][nt][3]);
                }
            }
        }
        __syncthreads();

        // ---- epilogue rec0: h0(s) (critical-path store) ----
        if (s < SEQ) {
            __half* hw = h0buf[s % 3];
#pragma unroll
            for (int it = 0; it < 2; it++) {
                int idx = tid + it * NTHR;
                int b = idx >> 3, j = idx & 7;
                int col = j << 2;
                float4 p0 = *reinterpret_cast<const float4*>(Ps0 + 0 * 64 * PS_STRIDE + b * PS_STRIDE + col);
                float4 p1 = *reinterpret_cast<const float4*>(Ps0 + 1 * 64 * PS_STRIDE + b * PS_STRIDE + col);
                float4 p2 = *reinterpret_cast<const float4*>(Ps0 + 2 * 64 * PS_STRIDE + b * PS_STRIDE + col);
                float4 p3 = *reinterpret_cast<const float4*>(Ps0 + 3 * 64 * PS_STRIDE + b * PS_STRIDE + col);

                float pi  = xv[it].x + ((p0.x + p1.x) + (p2.x + p3.x));
                float pfv = xv[it].y + ((p0.y + p1.y) + (p2.y + p3.y));
                float pg  = xv[it].z + ((p0.z + p1.z) + (p2.z + p3.z));
                float po  = xv[it].w + ((p0.w + p1.w) + (p2.w + p3.w));

                float gi = sigmoidf_(pi);
                float gf = sigmoidf_(pfv);
                float gg = tanhfast(pg);
                float go = sigmoidf_(po);

                float cv = gf * c0reg[it] + gi * gg;
                c0reg[it] = cv;
                float hv = go * tanhfast(cv);
                hw[b * HDIM + hperm16(J0 + j)] = __float2half(hv);
            }
        }

        // ---- epilogue rec1: h1(s-2) (critical store); seq/cdump deferred ----
        float hv1[2]; float cv1[2];
        if (s >= 2) {
            __half* hw = h1buf[s & 1];
#pragma unroll
            for (int it = 0; it < 2; it++) {
                int idx = tid + it * NTHR;
                int b = idx >> 3, j = idx & 7;
                int col = j << 2;
                float4 p0 = *reinterpret_cast<const float4*>(Ps1 + 0 * 64 * PS_STRIDE + b * PS_STRIDE + col);
                float4 p1 = *reinterpret_cast<const float4*>(Ps1 + 1 * 64 * PS_STRIDE + b * PS_STRIDE + col);
                float4 p2 = *reinterpret_cast<const float4*>(Ps1 + 2 * 64 * PS_STRIDE + b * PS_STRIDE + col);
                float4 p3 = *reinterpret_cast<const float4*>(Ps1 + 3 * 64 * PS_STRIDE + b * PS_STRIDE + col);

                float pi  = bs1[it].x + rc[it].x + ((p0.x + p1.x) + (p2.x + p3.x));
                float pfv = bs1[it].y + rc[it].y + ((p0.y + p1.y) + (p2.y + p3.y));
                float pg  = bs1[it].z + rc[it].z + ((p0.z + p1.z) + (p2.z + p3.z));
                float po  = bs1[it].w + rc[it].w + ((p0.w + p1.w) + (p2.w + p3.w));

                float gi = sigmoidf_(pi);
                float gf = sigmoidf_(pfv);
                float gg = tanhfast(pg);
                float go = sigmoidf_(po);

                float cv = gf * c1reg[it] + gi * gg;
                c1reg[it] = cv;
                float hv = go * tanhfast(cv);
                cv1[it] = cv; hv1[it] = hv;

                int J = J0 + j;
                hw[b * HDIM + hperm16(J)] = __float2half(hv);
            }
        }

        __syncthreads();
        if (tid == 0) st_rel(&g_flags[blockIdx.x], base + 2 + (unsigned)s);

        // ---- deferred non-critical stores (after flag release) ----
        if (s >= 2) {
            float* so = seq_out + (size_t)(s - 2) * BS * HDIM;
#pragma unroll
            for (int it = 0; it < 2; it++) {
                int idx = tid + it * NTHR;
                int b = idx >> 3, j = idx & 7;
                int J = J0 + j;
                so[(size_t)b * HDIM + J] = hv1[it];
                if (s == SEQ + 1) cdump[b * HDIM + J] = cv1[it];
            }
        }
    }
}

// ---------------- tail: (h, c) after the sequence --------------------------------
__global__ void copy_tail(const float* __restrict__ hsrc, const float* __restrict__ csrc,
                          float* __restrict__ dst) {
    int i = blockIdx.x * blockDim.x + threadIdx.x;
    if (i < BS * HDIM) {
        dst[i] = hsrc[i];
        dst[BS * HDIM + i] = csrc[i];
    }
}

// ---------------- launcher --------------------------------------------------------
extern "C" void kernel_launch(void* const* d_in, const int* in_sizes, int n_in,
                              void* d_out, int out_size) {
    (void)in_sizes; (void)n_in;

    const float* x     = (const float*)d_in[0];
    const float* Wii0  = (const float*)d_in[1];
    const float* Wii   = (const float*)d_in[2];
    const float* Whi   = (const float*)d_in[3];
    const float* Wif0  = (const float*)d_in[4];
    const float* Wif   = (const float*)d_in[5];
    const float* Whf   = (const float*)d_in[6];
    const float* Wig0  = (const float*)d_in[7];
    const float* Wig   = (const float*)d_in[8];
    const float* Whg   = (const float*)d_in[9];
    const float* Wio0  = (const float*)d_in[10];
    const float* Wio   = (const float*)d_in[11];
    const float* Who   = (const float*)d_in[12];
    const float* bi    = (const float*)d_in[13];
    const float* bf    = (const float*)d_in[14];
    const float* bg    = (const float*)d_in[15];
    const float* bo    = (const float*)d_in[16];

    float *pBias, *pXw, *pC;
    __half *pWx0h, *pWx1h, *pWhh, *pAh, *pH0A, *pH0B, *pH0C, *pH1A, *pH1B;
    cudaGetSymbolAddress((void**)&pWx0h, g_Wx0h);
    cudaGetSymbolAddress((void**)&pWx1h, g_Wx1h);
    cudaGetSymbolAddress((void**)&pWhh,  g_Whh);
    cudaGetSymbolAddress((void**)&pBias, g_bias);
    cudaGetSymbolAddress((void**)&pXw,   g_xw);
    cudaGetSymbolAddress((void**)&pAh,   g_Ah);
    cudaGetSymbolAddress((void**)&pH0A,  g_h0A);
    cudaGetSymbolAddress((void**)&pH0B,  g_h0B);
    cudaGetSymbolAddress((void**)&pH0C,  g_h0C);
    cudaGetSymbolAddress((void**)&pH1A,  g_h1A);
    cudaGetSymbolAddress((void**)&pH1B,  g_h1B);
    cudaGetSymbolAddress((void**)&pC,    g_c);

    float* out = (float*)d_out;

    static bool attr_set = false;
    if (!attr_set) {
        cudaFuncSetAttribute(lstm_fused,
                             cudaFuncAttributeMaxDynamicSharedMemorySize, SMEM_BYTES);
        cudaFuncSetAttribute(gemm_xw_f16,
                             cudaFuncAttributeMaxDynamicSharedMemorySize, GEMM_SMEM);
        attr_set = true;
    }

    // launch order: pack_all, cvtA, gemm0, lstm_fused (4th = ncu-profiled)
    pack_all<<<3073, 256>>>(Wii0, Wif0, Wig0, Wio0,
                            Wii,  Wif,  Wig,  Wio,
                            Whi,  Whf,  Whg,  Who,
                            bi, bf, bg, bo,
                            pWx0h, pWx1h, pWhh, pBias);
    {
        int n = SEQ * BS * IN_DIM;
        cvtA<<<(n / 2 + 255) / 256, 256>>>(x, pAh, n);
    }

    const dim3 gemm_grid(G4 / 128, (SEQ * BS) / 128);  // (32, 256)
    gemm_xw_f16<<<gemm_grid, 256, GEMM_SMEM>>>(pAh, pWx0h, pXw, pBias);

    lstm_fused<<<NCTA, NTHR, SMEM_BYTES>>>(pXw, pH0A, pH0B, pH0C, pH1A, pH1B, pC, out);

    // tail: final (h, c) of layer 1. h final = seq output at t = SEQ-1.
    size_t seqN = (size_t)SEQ * BS * HDIM;
    if ((size_t)out_size >= seqN + 2 * (size_t)BS * HDIM) {
        copy_tail<<<(BS * HDIM + 255) / 256, 256>>>(out + seqN - (size_t)BS * HDIM,
                                                    pC, out + seqN);
    }
}

// round 12
// speedup vs baseline: 1.1484x; 1.1484x over previous
#include <cuda_runtime.h>
#include <cuda_fp16.h>
#include <cstdint>

#define SEQ 512
#define BS 64
#define IN_DIM 1024
#define HDIM 1024
#define G4 4096           // 4 gates * H, packed as [k][j*4 + gate]
#define KD 1024
#define NCTA 128
#define NTHR 256          // pack/gemm kernels
#define LTHR 512          // lstm_fused: 16 warps = 4 K-slices x 4 M-quarters

// ---------------- device scratch (allocation rules forbid cudaMalloc) -----------
__device__ __half g_Wx0h[(size_t)G4 * KD];        // layer0 input W, [n][kperm] fp16
__device__ __half g_Wx1h[(size_t)G4 * KD];        // layer1 input W, [n][kperm] fp16
__device__ __half g_Whh [(size_t)G4 * KD];        // recurrent W,   [n][kperm] fp16
__device__ float  g_bias[G4];
__device__ float  g_xw [(size_t)SEQ * BS * G4];   // X@Wx0 + b (layer 0)
__device__ __half g_Ah [(size_t)SEQ * BS * KD];   // GEMM A, fp16 [m][kperm]
__device__ __half g_h0A[BS * HDIM];               // layer0 h ring-of-3 (fp16 perm)
__device__ __half g_h0B[BS * HDIM];
__device__ __half g_h0C[BS * HDIM];
__device__ __half g_h1A[BS * HDIM];               // layer1 h ring-of-2 (fp16 perm)
__device__ __half g_h1B[BS * HDIM];
__device__ float  g_c [BS * HDIM];

// monotonic per-CTA step flags (graph-replay safe: base re-read each launch)
__device__ __align__(16) unsigned g_flags[NCTA];

// ---------------- helpers -------------------------------------------------------
__device__ __forceinline__ void mma_f16(float& c0, float& c1, float& c2, float& c3,
                                        unsigned a0, unsigned a1, unsigned a2, unsigned a3,
                                        unsigned b0, unsigned b1) {
    asm volatile(
        "mma.sync.aligned.m16n8k16.row.col.f32.f16.f16.f32 "
        "{%0,%1,%2,%3}, {%4,%5,%6,%7}, {%8,%9}, {%0,%1,%2,%3};"
        : "+f"(c0), "+f"(c1), "+f"(c2), "+f"(c3)
        : "r"(a0), "r"(a1), "r"(a2), "r"(a3), "r"(b0), "r"(b1));
}

__device__ __forceinline__ float sigmoidf_(float x) {
    return 1.0f / (1.0f + __expf(-x));
}
__device__ __forceinline__ float tanhfast(float x) {
    float y; asm("tanh.approx.f32 %0, %1;" : "=f"(y) : "f"(x)); return y;
}

__device__ __forceinline__ unsigned ld_acq(const unsigned* p) {
    unsigned v;
    asm volatile("ld.acquire.gpu.global.u32 %0, [%1];" : "=r"(v) : "l"(p) : "memory");
    return v;
}
__device__ __forceinline__ void st_rel(unsigned* p, unsigned v) {
    asm volatile("st.release.gpu.global.u32 [%0], %1;" :: "l"(p), "r"(v) : "memory");
}

__device__ __forceinline__ void cpa16(void* s, const void* g) {
    unsigned sa = (unsigned)__cvta_generic_to_shared(s);
    asm volatile("cp.async.cg.shared.global [%0], [%1], 16;" :: "r"(sa), "l"(g));
}
__device__ __forceinline__ void cpa_commit() {
    asm volatile("cp.async.commit_group;");
}
__device__ __forceinline__ void cpa_wait1() {
    asm volatile("cp.async.wait_group 1;");
}

// fp16 k-permutation within each 32-k block
__device__ __host__ __forceinline__ int hperm16(int k) {
    int t = k & 31;
    int tile = t >> 4;
    int u = t & 15;
    int b = u & 1;
    int tg = (u >> 1) & 3;
    int c = u >> 3;
    return (k & ~31) | (tg * 8 + tile * 4 + c * 2 + b);
}

// ---------------- fused packing kernel --------------------------------------------
__global__ void pack_all(
    const float* __restrict__ Wi0, const float* __restrict__ Wf0,
    const float* __restrict__ Wg0, const float* __restrict__ Wo0,
    const float* __restrict__ Wi1, const float* __restrict__ Wf1,
    const float* __restrict__ Wg1, const float* __restrict__ Wo1,
    const float* __restrict__ Whi, const float* __restrict__ Whf,
    const float* __restrict__ Whg, const float* __restrict__ Who,
    const float* __restrict__ bi,  const float* __restrict__ bf,
    const float* __restrict__ bg,  const float* __restrict__ bo,
    __half* __restrict__ Wx0h, __half* __restrict__ Wx1h,
    __half* __restrict__ Whh, float* __restrict__ bias) {
    const int bid = blockIdx.x;
    const int tid = threadIdx.x;
    if (bid < 3072) {
        const int set = bid >> 10;
        const int rem = bid & 1023;
        const int gate = rem >> 8;
        const int tile = rem & 255;
        const float* W;
        __half* dst;
        if (set == 0) {
            W = (gate == 0) ? Wi0 : (gate == 1) ? Wf0 : (gate == 2) ? Wg0 : Wo0;
            dst = Wx0h;
        } else if (set == 1) {
            W = (gate == 0) ? Wi1 : (gate == 1) ? Wf1 : (gate == 2) ? Wg1 : Wo1;
            dst = Wx1h;
        } else {
            W = (gate == 0) ? Whi : (gate == 1) ? Whf : (gate == 2) ? Whg : Who;
            dst = Whh;
        }
        const int k0 = (tile & 15) * 64, j0 = (tile >> 4) * 64;
        __shared__ __half t[64][65];
#pragma unroll
        for (int it = 0; it < 16; it++) {
            int v = tid + it * 256;
            int ky = v >> 6, jx = v & 63;
            t[ky][jx] = __float2half(W[(size_t)(k0 + ky) * HDIM + j0 + jx]);
        }
        __syncthreads();
#pragma unroll
        for (int it = 0; it < 16; it++) {
            int v = tid + it * 256;
            int jy = v >> 6, kx = v & 63;
            int n = (j0 + jy) * 4 + gate;
            dst[(size_t)n * KD + hperm16(k0 + kx)] = t[kx][jy];
        }
    } else {
#pragma unroll
        for (int e = 0; e < 4; e++) {
            int j = tid + e * 256;
            float4 v;
            v.x = bi[j]; v.y = bf[j]; v.z = bg[j]; v.w = bo[j];
            reinterpret_cast<float4*>(bias)[j] = v;
        }
    }
}

// A conversion: fp32 [m][k] -> fp16 [m][hperm16(k)]
__global__ void cvtA(const float* __restrict__ src, __half* __restrict__ dst, int total) {
    int i2 = blockIdx.x * blockDim.x + threadIdx.x;
    int idx = i2 * 2;
    if (idx >= total) return;
    float2 v = *reinterpret_cast<const float2*>(src + idx);
    int m = idx >> 10, k = idx & 1023;
    *reinterpret_cast<__half2*>(dst + ((size_t)m << 10) + hperm16(k)) =
        __floats2half2_rn(v.x, v.y);
}

// ---------------- big input-projection GEMM (fp16, cp.async 2-stage) -------------
#define GSTR 96
#define GSTAGE (128 * GSTR)

__global__ void __launch_bounds__(256, 2)
gemm_xw_f16(const __half* __restrict__ A, const __half* __restrict__ B,
            float* __restrict__ C, const float* __restrict__ bias) {
    extern __shared__ __align__(16) __half gs[];
    const int m0 = blockIdx.y * 128;
    const int n0 = blockIdx.x * 128;
    const int tid  = threadIdx.x;
    const int warp = tid >> 5, lane = tid & 31;
    const int grp  = lane >> 2, tg = lane & 3;
    const int wm = warp & 1;
    const int wn = warp >> 1;

    const int cc = tid & 7;
    const int rr = tid >> 3;

    auto issue = [&](int st, int kofs) {
        __half* As = gs + st * GSTAGE;
        __half* Bs = gs + 2 * GSTAGE + st * GSTAGE;
#pragma unroll
        for (int i = 0; i < 4; i++) {
            int row = rr + i * 32;
            cpa16(As + row * GSTR + cc * 8,
                  A + (size_t)(m0 + row) * KD + kofs + cc * 8);
            cpa16(Bs + row * GSTR + cc * 8,
                  B + (size_t)(n0 + row) * KD + kofs + cc * 8);
        }
        cpa_commit();
    };

    issue(0, 0);
    issue(1, 64);

    float acc[4][4][4];
#pragma unroll
    for (int mi = 0; mi < 4; mi++)
#pragma unroll
        for (int ni = 0; ni < 4; ni++)
#pragma unroll
            for (int q = 0; q < 4; q++) acc[mi][ni][q] = 0.0f;

    for (int kt = 0; kt < 16; kt++) {
        cpa_wait1();
        __syncthreads();
        const __half* As = gs + (kt & 1) * GSTAGE;
        const __half* Bs = gs + 2 * GSTAGE + (kt & 1) * GSTAGE;

#pragma unroll
        for (int g32 = 0; g32 < 2; g32++) {
            const int ko = g32 * 32 + tg * 8;
            uint4 Bf[4];
#pragma unroll
            for (int ni = 0; ni < 4; ni++) {
                const int c = wn * 32 + ni * 8 + grp;
                Bf[ni] = *reinterpret_cast<const uint4*>(Bs + c * GSTR + ko);
            }
#pragma unroll
            for (int mi = 0; mi < 4; mi++) {
                const int r = wm * 64 + mi * 16 + grp;
                uint4 Aa = *reinterpret_cast<const uint4*>(As + (r    ) * GSTR + ko);
                uint4 Ab = *reinterpret_cast<const uint4*>(As + (r + 8) * GSTR + ko);
#pragma unroll
                for (int ni = 0; ni < 4; ni++) {
                    mma_f16(acc[mi][ni][0], acc[mi][ni][1], acc[mi][ni][2], acc[mi][ni][3],
                            Aa.x, Ab.x, Aa.y, Ab.y, Bf[ni].x, Bf[ni].y);
                    mma_f16(acc[mi][ni][0], acc[mi][ni][1], acc[mi][ni][2], acc[mi][ni][3],
                            Aa.z, Ab.z, Aa.w, Ab.w, Bf[ni].z, Bf[ni].w);
                }
            }
        }
        __syncthreads();
        if (kt < 14) issue(kt & 1, (kt + 2) * 64);
        else cpa_commit();
    }

#pragma unroll
    for (int mi = 0; mi < 4; mi++) {
        const int r = m0 + wm * 64 + mi * 16 + grp;
#pragma unroll
        for (int ni = 0; ni < 4; ni++) {
            const int c = n0 + wn * 32 + ni * 8 + tg * 2;
            float2 bv = *reinterpret_cast<const float2*>(bias + c);
            float2 o0, o1;
            o0.x = acc[mi][ni][0] + bv.x;  o0.y = acc[mi][ni][1] + bv.y;
            o1.x = acc[mi][ni][2] + bv.x;  o1.y = acc[mi][ni][3] + bv.y;
            *reinterpret_cast<float2*>(C + (size_t)r * G4 + c)       = o0;
            *reinterpret_cast<float2*>(C + (size_t)(r + 8) * G4 + c) = o1;
        }
    }
}
#define GEMM_SMEM (4 * GSTAGE * (int)sizeof(__half))   // 96 KB

// ---------------- fused two-layer persistent recurrence (512 threads) -------------
// R10 algorithm, re-mapped to 16 warps = 4 K-slices x 4 M-quarters (m16 tiles).
// Round s (0..513):
//   PRE-WAIT : rc = carry partials (h0(s-2)@Wx1 from round s-1); xw(s) prefetch
//   WAIT(s)  : 128 threads ld.acquire one flag each + __syncthreads_and
//   MERGED   : X = h0(s-1), Y = h1(s-3), both depth-1 streamed; per 32-k group
//              one Bv(Wh) feeds acc0 (X@Wh) and acc1 (Y@Wh); Cv(Wx1) feeds accC.
//   EPILOGUE : h0(s), h1(s-2) stores -> flag -> deferred seq/cdump stores
#define WT_STRIDE 1056              // halves
#define PS_STRIDE 36                // floats (Ps0/Ps1), halves (PsC)
#define WSLICE (32 * WT_STRIDE)     // halves per weight slice
#define PSLICE (4 * 64 * PS_STRIDE) // floats per fp32 partial buffer
#define SMEM_BYTES (2 * WSLICE * 2 + 2 * PSLICE * 4 + PSLICE * 2)   // 222 KB

__global__ void __launch_bounds__(LTHR, 1)
lstm_fused(const float* __restrict__ xw,
           __half* __restrict__ h0A, __half* __restrict__ h0B, __half* __restrict__ h0C,
           __half* __restrict__ h1A, __half* __restrict__ h1B,
           float* __restrict__ cdump, float* __restrict__ seq_out) {
    extern __shared__ __align__(16) unsigned char smem_raw[];
    __half* WhS  = reinterpret_cast<__half*>(smem_raw);              // [32][WT_STRIDE]
    __half* Wx1S = WhS + WSLICE;                                     // [32][WT_STRIDE]
    float*  Ps0  = reinterpret_cast<float*>(smem_raw + 2 * WSLICE * 2);
    float*  Ps1  = Ps0 + PSLICE;
    __half* PsC  = reinterpret_cast<__half*>(Ps1 + PSLICE);          // fp16 carry

    const int tid  = threadIdx.x;
    const int warp = tid >> 5, lane = tid & 31;
    const int grp  = lane >> 2, tg = lane & 3;
    const int wmq = warp & 3;                // M quarter: rows wmq*16..+15
    const int ks = warp >> 2;                // K slice: [ks*256, +256)

    const int n0 = blockIdx.x * 32;          // packed gate column base
    const int J0 = blockIdx.x * 8;           // hidden-unit base

    const unsigned base = g_flags[blockIdx.x];

    // ---- preload weight slices ([n][kperm] fp16: raw vector copies) ----
    for (int idx = tid; idx < 32 * 128; idx += LTHR) {
        int c = idx >> 7, ch = idx & 127;
        *reinterpret_cast<uint4*>(WhS  + c * WT_STRIDE + ch * 8) =
            *reinterpret_cast<const uint4*>(g_Whh  + (size_t)(n0 + c) * KD + ch * 8);
        *reinterpret_cast<uint4*>(Wx1S + c * WT_STRIDE + ch * 8) =
            *reinterpret_cast<const uint4*>(g_Wx1h + (size_t)(n0 + c) * KD + ch * 8);
    }

    // ---- zero own h columns (all 5 buffers) + PsC ----
    {
        int b = tid >> 3, j = tid & 7;       // 512 threads = 512 items exactly
        int p = b * HDIM + hperm16(J0 + j);
        __half z = __float2half(0.0f);
        h0A[p] = z; h0B[p] = z; h0C[p] = z; h1A[p] = z; h1B[p] = z;
    }
    for (int idx = tid; idx < PSLICE / 2; idx += LTHR)
        reinterpret_cast<uint*>(PsC)[idx] = 0u;

    // ---- per-thread layer-1 bias (one item per thread) ----
    const int eb = tid >> 3;                 // epilogue batch row
    const int ej = tid & 7;                  // epilogue unit index
    const int ecol = ej << 2;
    float4 bs1 = *reinterpret_cast<const float4*>(g_bias + n0 + ecol);

    __syncthreads();
    if (tid == 0) st_rel(&g_flags[blockIdx.x], base + 1);

    float c0reg = 0.0f;
    float c1reg = 0.0f;
    __half* h0buf[3] = {h0A, h0B, h0C};
    __half* h1buf[2] = {h1A, h1B};

    const int r0 = wmq * 16 + grp;           // lane's base row (and r0+8)
    const int kbase = ks * 256;
    const size_t laneoff = kbase + tg * 8;

    for (int s = 0; s <= SEQ + 1; s++) {
        // ---- PRE-WAIT: carry rc = h0(s-2)@Wx1 partials (own SMEM) ----
        float4 rc;
        {
            const __half* cb = PsC + eb * PS_STRIDE + ecol;
            float4 rs = make_float4(0.f, 0.f, 0.f, 0.f);
#pragma unroll
            for (int k4 = 0; k4 < 4; k4++) {
                uint2 raw = *reinterpret_cast<const uint2*>(cb + k4 * 64 * PS_STRIDE);
                float2 f0 = __half22float2(*reinterpret_cast<__half2*>(&raw.x));
                float2 f1 = __half22float2(*reinterpret_cast<__half2*>(&raw.y));
                rs.x += f0.x; rs.y += f0.y; rs.z += f1.x; rs.w += f1.y;
            }
            rc = rs;
        }

        // ---- prefetch xw(s) ----
        float4 xv = make_float4(0.f, 0.f, 0.f, 0.f);
        if (s < SEQ) {
            const float* xw_t = xw + (size_t)s * BS * G4;
            xv = *reinterpret_cast<const float4*>(xw_t + (size_t)eb * G4 + n0 + ecol);
        }

        // ---- WAIT: all CTAs finished round s-1 ----
        {
            const unsigned target = base + 1 + (unsigned)s;
            bool ok;
            do {
                unsigned v = (tid < NCTA) ? ld_acq(&g_flags[tid]) : target;
                ok = (int)(v - target) >= 0;
            } while (!__syncthreads_and(ok));
        }

        // ---- MERGED phase: X = h0(s-1), Y = h1(s-3), both depth-1 ----
        {
            const __half* xr = h0buf[(s + 2) % 3];
            const __half* yr = h1buf[(s + 1) & 1];
            const __half* xp0 = xr + (size_t)(r0    ) * KD + laneoff;
            const __half* xp1 = xr + (size_t)(r0 + 8) * KD + laneoff;
            const __half* yp0 = yr + (size_t)(r0    ) * KD + laneoff;
            const __half* yp1 = yr + (size_t)(r0 + 8) * KD + laneoff;

            float acc0[4][4], acc1[4][4], accC[4][4];
#pragma unroll
            for (int nt = 0; nt < 4; nt++)
#pragma unroll
                for (int q = 0; q < 4; q++) {
                    acc0[nt][q] = 0.0f; acc1[nt][q] = 0.0f; accC[nt][q] = 0.0f;
                }

            uint4 X0 = *reinterpret_cast<const uint4*>(xp0);
            uint4 X1 = *reinterpret_cast<const uint4*>(xp1);
            uint4 Y0 = *reinterpret_cast<const uint4*>(yp0);
            uint4 Y1 = *reinterpret_cast<const uint4*>(yp1);

#pragma unroll
            for (int g = 0; g < 8; g++) {
                uint4 NX0, NX1, NY0, NY1;
                if (g < 7) {
                    const int off = (g + 1) * 32;
                    NX0 = *reinterpret_cast<const uint4*>(xp0 + off);
                    NX1 = *reinterpret_cast<const uint4*>(xp1 + off);
                    NY0 = *reinterpret_cast<const uint4*>(yp0 + off);
                    NY1 = *reinterpret_cast<const uint4*>(yp1 + off);
                }
#pragma unroll
                for (int nt = 0; nt < 4; nt++) {
                    const int c = nt * 8 + grp;
                    uint4 Bv = *reinterpret_cast<const uint4*>(
                        WhS + c * WT_STRIDE + kbase + g * 32 + tg * 8);
                    uint4 Cv = *reinterpret_cast<const uint4*>(
                        Wx1S + c * WT_STRIDE + kbase + g * 32 + tg * 8);
                    // acc0 = X @ Wh
                    mma_f16(acc0[nt][0], acc0[nt][1], acc0[nt][2], acc0[nt][3],
                            X0.x, X1.x, X0.y, X1.y, Bv.x, Bv.y);
                    mma_f16(acc0[nt][0], acc0[nt][1], acc0[nt][2], acc0[nt][3],
                            X0.z, X1.z, X0.w, X1.w, Bv.z, Bv.w);
                    // acc1 = Y @ Wh (same Bv)
                    mma_f16(acc1[nt][0], acc1[nt][1], acc1[nt][2], acc1[nt][3],
                            Y0.x, Y1.x, Y0.y, Y1.y, Bv.x, Bv.y);
                    mma_f16(acc1[nt][0], acc1[nt][1], acc1[nt][2], acc1[nt][3],
                            Y0.z, Y1.z, Y0.w, Y1.w, Bv.z, Bv.w);
                    // accC = X @ Wx1
                    mma_f16(accC[nt][0], accC[nt][1], accC[nt][2], accC[nt][3],
                            X0.x, X1.x, X0.y, X1.y, Cv.x, Cv.y);
                    mma_f16(accC[nt][0], accC[nt][1], accC[nt][2], accC[nt][3],
                            X0.z, X1.z, X0.w, X1.w, Cv.z, Cv.w);
                }
                X0 = NX0; X1 = NX1; Y0 = NY0; Y1 = NY1;
            }

            // spill: acc0/acc1 fp32, accC fp16 carry for round s+1
            float*  P0s = Ps0 + ks * 64 * PS_STRIDE;
            float*  P1s = Ps1 + ks * 64 * PS_STRIDE;
            __half* PCs = PsC + ks * 64 * PS_STRIDE;
            const int r = wmq * 16 + grp;
#pragma unroll
            for (int nt = 0; nt < 4; nt++) {
                const int c = nt * 8 + tg * 2;
                *reinterpret_cast<float2*>(P0s + (r    ) * PS_STRIDE + c) =
                    make_float2(acc0[nt][0], acc0[nt][1]);
                *reinterpret_cast<float2*>(P0s + (r + 8) * PS_STRIDE + c) =
                    make_float2(acc0[nt][2], acc0[nt][3]);
                *reinterpret_cast<float2*>(P1s + (r    ) * PS_STRIDE + c) =
                    make_float2(acc1[nt][0], acc1[nt][1]);
                *reinterpret_cast<float2*>(P1s + (r + 8) * PS_STRIDE + c) =
                    make_float2(acc1[nt][2], acc1[nt][3]);
                *reinterpret_cast<__half2*>(PCs + (r    ) * PS_STRIDE + c) =
                    __floats2half2_rn(accC[nt][0], accC[nt][1]);
                *reinterpret_cast<__half2*>(PCs + (r + 8) * PS_STRIDE + c) =
                    __floats2half2_rn(accC[nt][2], accC[nt][3]);
            }
        }
        __syncthreads();

        // ---- epilogue rec0: h0(s) (critical-path store; 1 item/thread) ----
        if (s < SEQ) {
            __half* hw = h0buf[s % 3];
            float4 p0 = *reinterpret_cast<const float4*>(Ps0 + 0 * 64 * PS_STRIDE + eb * PS_STRIDE + ecol);
            float4 p1 = *reinterpret_cast<const float4*>(Ps0 + 1 * 64 * PS_STRIDE + eb * PS_STRIDE + ecol);
            float4 p2 = *reinterpret_cast<const float4*>(Ps0 + 2 * 64 * PS_STRIDE + eb * PS_STRIDE + ecol);
            float4 p3 = *reinterpret_cast<const float4*>(Ps0 + 3 * 64 * PS_STRIDE + eb * PS_STRIDE + ecol);

            float pi  = xv.x + ((p0.x + p1.x) + (p2.x + p3.x));
            float pfv = xv.y + ((p0.y + p1.y) + (p2.y + p3.y));
            float pg  = xv.z + ((p0.z + p1.z) + (p2.z + p3.z));
            float po  = xv.w + ((p0.w + p1.w) + (p2.w + p3.w));

            float gi = sigmoidf_(pi);
            float gf = sigmoidf_(pfv);
            float gg = tanhfast(pg);
            float go = sigmoidf_(po);

            float cv = gf * c0reg + gi * gg;
            c0reg = cv;
            float hv = go * tanhfast(cv);
            hw[eb * HDIM + hperm16(J0 + ej)] = __float2half(hv);
        }

        // ---- epilogue rec1: h1(s-2) (critical store); seq/cdump deferred ----
        float hv1 = 0.0f, cv1 = 0.0f;
        if (s >= 2) {
            __half* hw = h1buf[s & 1];
            float4 p0 = *reinterpret_cast<const float4*>(Ps1 + 0 * 64 * PS_STRIDE + eb * PS_STRIDE + ecol);
            float4 p1 = *reinterpret_cast<const float4*>(Ps1 + 1 * 64 * PS_STRIDE + eb * PS_STRIDE + ecol);
            float4 p2 = *reinterpret_cast<const float4*>(Ps1 + 2 * 64 * PS_STRIDE + eb * PS_STRIDE + ecol);
            float4 p3 = *reinterpret_cast<const float4*>(Ps1 + 3 * 64 * PS_STRIDE + eb * PS_STRIDE + ecol);

            float pi  = bs1.x + rc.x + ((p0.x + p1.x) + (p2.x + p3.x));
            float pfv = bs1.y + rc.y + ((p0.y + p1.y) + (p2.y + p3.y));
            float pg  = bs1.z + rc.z + ((p0.z + p1.z) + (p2.z + p3.z));
            float po  = bs1.w + rc.w + ((p0.w + p1.w) + (p2.w + p3.w));

            float gi = sigmoidf_(pi);
            float gf = sigmoidf_(pfv);
            float gg = tanhfast(pg);
            float go = sigmoidf_(po);

            float cv = gf * c1reg + gi * gg;
            c1reg = cv;
            float hv = go * tanhfast(cv);
            cv1 = cv; hv1 = hv;

            hw[eb * HDIM + hperm16(J0 + ej)] = __float2half(hv);
        }

        __syncthreads();
        if (tid == 0) st_rel(&g_flags[blockIdx.x], base + 2 + (unsigned)s);

        // ---- deferred non-critical stores (after flag release) ----
        if (s >= 2) {
            float* so = seq_out + (size_t)(s - 2) * BS * HDIM;
            int J = J0 + ej;
            so[(size_t)eb * HDIM + J] = hv1;
            if (s == SEQ + 1) cdump[eb * HDIM + J] = cv1;
        }
    }
}

// ---------------- tail: (h, c) after the sequence --------------------------------
__global__ void copy_tail(const float* __restrict__ hsrc, const float* __restrict__ csrc,
                          float* __restrict__ dst) {
    int i = blockIdx.x * blockDim.x + threadIdx.x;
    if (i < BS * HDIM) {
        dst[i] = hsrc[i];
        dst[BS * HDIM + i] = csrc[i];
    }
}

// ---------------- launcher --------------------------------------------------------
extern "C" void kernel_launch(void* const* d_in, const int* in_sizes, int n_in,
                              void* d_out, int out_size) {
    (void)in_sizes; (void)n_in;

    const float* x     = (const float*)d_in[0];
    const float* Wii0  = (const float*)d_in[1];
    const float* Wii   = (const float*)d_in[2];
    const float* Whi   = (const float*)d_in[3];
    const float* Wif0  = (const float*)d_in[4];
    const float* Wif   = (const float*)d_in[5];
    const float* Whf   = (const float*)d_in[6];
    const float* Wig0  = (const float*)d_in[7];
    const float* Wig   = (const float*)d_in[8];
    const float* Whg   = (const float*)d_in[9];
    const float* Wio0  = (const float*)d_in[10];
    const float* Wio   = (const float*)d_in[11];
    const float* Who   = (const float*)d_in[12];
    const float* bi    = (const float*)d_in[13];
    const float* bf    = (const float*)d_in[14];
    const float* bg    = (const float*)d_in[15];
    const float* bo    = (const float*)d_in[16];

    float *pBias, *pXw, *pC;
    __half *pWx0h, *pWx1h, *pWhh, *pAh, *pH0A, *pH0B, *pH0C, *pH1A, *pH1B;
    cudaGetSymbolAddress((void**)&pWx0h, g_Wx0h);
    cudaGetSymbolAddress((void**)&pWx1h, g_Wx1h);
    cudaGetSymbolAddress((void**)&pWhh,  g_Whh);
    cudaGetSymbolAddress((void**)&pBias, g_bias);
    cudaGetSymbolAddress((void**)&pXw,   g_xw);
    cudaGetSymbolAddress((void**)&pAh,   g_Ah);
    cudaGetSymbolAddress((void**)&pH0A,  g_h0A);
    cudaGetSymbolAddress((void**)&pH0B,  g_h0B);
    cudaGetSymbolAddress((void**)&pH0C,  g_h0C);
    cudaGetSymbolAddress((void**)&pH1A,  g_h1A);
    cudaGetSymbolAddress((void**)&pH1B,  g_h1B);
    cudaGetSymbolAddress((void**)&pC,    g_c);

    float* out = (float*)d_out;

    static bool attr_set = false;
    if (!attr_set) {
        cudaFuncSetAttribute(lstm_fused,
                             cudaFuncAttributeMaxDynamicSharedMemorySize, SMEM_BYTES);
        cudaFuncSetAttribute(gemm_xw_f16,
                             cudaFuncAttributeMaxDynamicSharedMemorySize, GEMM_SMEM);
        attr_set = true;
    }

    // launch order: pack_all, cvtA, gemm0, lstm_fused (4th = ncu-profiled)
    pack_all<<<3073, 256>>>(Wii0, Wif0, Wig0, Wio0,
                            Wii,  Wif,  Wig,  Wio,
                            Whi,  Whf,  Whg,  Who,
                            bi, bf, bg, bo,
                            pWx0h, pWx1h, pWhh, pBias);
    {
        int n = SEQ * BS * IN_DIM;
        cvtA<<<(n / 2 + 255) / 256, 256>>>(x, pAh, n);
    }

    const dim3 gemm_grid(G4 / 128, (SEQ * BS) / 128);  // (32, 256)
    gemm_xw_f16<<<gemm_grid, 256, GEMM_SMEM>>>(pAh, pWx0h, pXw, pBias);

    lstm_fused<<<NCTA, LTHR, SMEM_BYTES>>>(pXw, pH0A, pH0B, pH0C, pH1A, pH1B, pC, out);

    // tail: final (h, c) of layer 1. h final = seq output at t = SEQ-1.
    size_t seqN = (size_t)SEQ * BS * HDIM;
    if ((size_t)out_size >= seqN + 2 * (size_t)BS * HDIM) {
        copy_tail<<<(BS * HDIM + 255) / 256, 256>>>(out + seqN - (size_t)BS * HDIM,
                                                    pC, out + seqN);
    }
}

// round 13
// speedup vs baseline: 2.1777x; 1.8964x over previous
#include <cuda_runtime.h>
#include <cuda_fp16.h>
#include <cstdint>

#define SEQ 512
#define BS 64
#define IN_DIM 1024
#define HDIM 1024
#define G4 4096           // 4 gates * H, packed as [k][j*4 + gate]
#define KD 1024
#define NCTA 128
#define NTHR 256

// ---------------- device scratch (allocation rules forbid cudaMalloc) -----------
__device__ __half g_Wx0h[(size_t)G4 * KD];        // layer0 input W, [n][kperm] fp16
__device__ __half g_Wx1h[(size_t)G4 * KD];        // layer1 input W, [n][kperm] fp16
__device__ __half g_Whh [(size_t)G4 * KD];        // recurrent W,   [n][kperm] fp16
__device__ float  g_bias[G4];
__device__ float  g_xw [(size_t)SEQ * BS * G4];   // X@Wx0 + b (layer 0)
__device__ __half g_Ah [(size_t)SEQ * BS * KD];   // GEMM A, fp16 [m][kperm]
__device__ __half g_h0A[BS * HDIM];               // layer0 h ring-of-3 (fp16 perm)
__device__ __half g_h0B[BS * HDIM];
__device__ __half g_h0C[BS * HDIM];
__device__ __half g_h1A[BS * HDIM];               // layer1 h ring-of-2 (fp16 perm)
__device__ __half g_h1B[BS * HDIM];
__device__ float  g_c [BS * HDIM];

// monotonic per-CTA step flags (graph-replay safe: base re-read each launch)
__device__ __align__(16) unsigned g_flags[NCTA];

// ---------------- helpers -------------------------------------------------------
__device__ __forceinline__ void mma_f16(float& c0, float& c1, float& c2, float& c3,
                                        unsigned a0, unsigned a1, unsigned a2, unsigned a3,
                                        unsigned b0, unsigned b1) {
    asm volatile(
        "mma.sync.aligned.m16n8k16.row.col.f32.f16.f16.f32 "
        "{%0,%1,%2,%3}, {%4,%5,%6,%7}, {%8,%9}, {%0,%1,%2,%3};"
        : "+f"(c0), "+f"(c1), "+f"(c2), "+f"(c3)
        : "r"(a0), "r"(a1), "r"(a2), "r"(a3), "r"(b0), "r"(b1));
}

__device__ __forceinline__ float sigmoidf_(float x) {
    return 1.0f / (1.0f + __expf(-x));
}
__device__ __forceinline__ float tanhfast(float x) {
    float y; asm("tanh.approx.f32 %0, %1;" : "=f"(y) : "f"(x)); return y;
}

__device__ __forceinline__ unsigned ld_acq(const unsigned* p) {
    unsigned v;
    asm volatile("ld.acquire.gpu.global.u32 %0, [%1];" : "=r"(v) : "l"(p) : "memory");
    return v;
}
__device__ __forceinline__ void st_rel(unsigned* p, unsigned v) {
    asm volatile("st.release.gpu.global.u32 [%0], %1;" :: "l"(p), "r"(v) : "memory");
}

__device__ __forceinline__ void cpa16(void* s, const void* g) {
    unsigned sa = (unsigned)__cvta_generic_to_shared(s);
    asm volatile("cp.async.cg.shared.global [%0], [%1], 16;" :: "r"(sa), "l"(g));
}
__device__ __forceinline__ void cpa_commit() {
    asm volatile("cp.async.commit_group;");
}
__device__ __forceinline__ void cpa_wait1() {
    asm volatile("cp.async.wait_group 1;");
}

// fp16 k-permutation within each 32-k block
__device__ __host__ __forceinline__ int hperm16(int k) {
    int t = k & 31;
    int tile = t >> 4;
    int u = t & 15;
    int b = u & 1;
    int tg = (u >> 1) & 3;
    int c = u >> 3;
    return (k & ~31) | (tg * 8 + tile * 4 + c * 2 + b);
}

// ---------------- fused packing kernel --------------------------------------------
__global__ void pack_all(
    const float* __restrict__ Wi0, const float* __restrict__ Wf0,
    const float* __restrict__ Wg0, const float* __restrict__ Wo0,
    const float* __restrict__ Wi1, const float* __restrict__ Wf1,
    const float* __restrict__ Wg1, const float* __restrict__ Wo1,
    const float* __restrict__ Whi, const float* __restrict__ Whf,
    const float* __restrict__ Whg, const float* __restrict__ Who,
    const float* __restrict__ bi,  const float* __restrict__ bf,
    const float* __restrict__ bg,  const float* __restrict__ bo,
    __half* __restrict__ Wx0h, __half* __restrict__ Wx1h,
    __half* __restrict__ Whh, float* __restrict__ bias) {
    const int bid = blockIdx.x;
    const int tid = threadIdx.x;
    if (bid < 3072) {
        const int set = bid >> 10;
        const int rem = bid & 1023;
        const int gate = rem >> 8;
        const int tile = rem & 255;
        const float* W;
        __half* dst;
        if (set == 0) {
            W = (gate == 0) ? Wi0 : (gate == 1) ? Wf0 : (gate == 2) ? Wg0 : Wo0;
            dst = Wx0h;
        } else if (set == 1) {
            W = (gate == 0) ? Wi1 : (gate == 1) ? Wf1 : (gate == 2) ? Wg1 : Wo1;
            dst = Wx1h;
        } else {
            W = (gate == 0) ? Whi : (gate == 1) ? Whf : (gate == 2) ? Whg : Who;
            dst = Whh;
        }
        const int k0 = (tile & 15) * 64, j0 = (tile >> 4) * 64;
        __shared__ __half t[64][65];
#pragma unroll
        for (int it = 0; it < 16; it++) {
            int v = tid + it * 256;
            int ky = v >> 6, jx = v & 63;
            t[ky][jx] = __float2half(W[(size_t)(k0 + ky) * HDIM + j0 + jx]);
        }
        __syncthreads();
#pragma unroll
        for (int it = 0; it < 16; it++) {
            int v = tid + it * 256;
            int jy = v >> 6, kx = v & 63;
            int n = (j0 + jy) * 4 + gate;
            dst[(size_t)n * KD + hperm16(k0 + kx)] = t[kx][jy];
        }
    } else {
#pragma unroll
        for (int e = 0; e < 4; e++) {
            int j = tid + e * 256;
            float4 v;
            v.x = bi[j]; v.y = bf[j]; v.z = bg[j]; v.w = bo[j];
            reinterpret_cast<float4*>(bias)[j] = v;
        }
    }
}

// A conversion: fp32 [m][k] -> fp16 [m][hperm16(k)]
__global__ void cvtA(const float* __restrict__ src, __half* __restrict__ dst, int total) {
    int i2 = blockIdx.x * blockDim.x + threadIdx.x;
    int idx = i2 * 2;
    if (idx >= total) return;
    float2 v = *reinterpret_cast<const float2*>(src + idx);
    int m = idx >> 10, k = idx & 1023;
    *reinterpret_cast<__half2*>(dst + ((size_t)m << 10) + hperm16(k)) =
        __floats2half2_rn(v.x, v.y);
}

// ---------------- big input-projection GEMM (fp16, cp.async 2-stage) -------------
#define GSTR 96
#define GSTAGE (128 * GSTR)

__global__ void __launch_bounds__(256, 2)
gemm_xw_f16(const __half* __restrict__ A, const __half* __restrict__ B,
            float* __restrict__ C, const float* __restrict__ bias) {
    extern __shared__ __align__(16) __half gs[];
    const int m0 = blockIdx.y * 128;
    const int n0 = blockIdx.x * 128;
    const int tid  = threadIdx.x;
    const int warp = tid >> 5, lane = tid & 31;
    const int grp  = lane >> 2, tg = lane & 3;
    const int wm = warp & 1;
    const int wn = warp >> 1;

    const int cc = tid & 7;
    const int rr = tid >> 3;

    auto issue = [&](int st, int kofs) {
        __half* As = gs + st * GSTAGE;
        __half* Bs = gs + 2 * GSTAGE + st * GSTAGE;
#pragma unroll
        for (int i = 0; i < 4; i++) {
            int row = rr + i * 32;
            cpa16(As + row * GSTR + cc * 8,
                  A + (size_t)(m0 + row) * KD + kofs + cc * 8);
            cpa16(Bs + row * GSTR + cc * 8,
                  B + (size_t)(n0 + row) * KD + kofs + cc * 8);
        }
        cpa_commit();
    };

    issue(0, 0);
    issue(1, 64);

    float acc[4][4][4];
#pragma unroll
    for (int mi = 0; mi < 4; mi++)
#pragma unroll
        for (int ni = 0; ni < 4; ni++)
#pragma unroll
            for (int q = 0; q < 4; q++) acc[mi][ni][q] = 0.0f;

    for (int kt = 0; kt < 16; kt++) {
        cpa_wait1();
        __syncthreads();
        const __half* As = gs + (kt & 1) * GSTAGE;
        const __half* Bs = gs + 2 * GSTAGE + (kt & 1) * GSTAGE;

#pragma unroll
        for (int g32 = 0; g32 < 2; g32++) {
            const int ko = g32 * 32 + tg * 8;
            uint4 Bf[4];
#pragma unroll
            for (int ni = 0; ni < 4; ni++) {
                const int c = wn * 32 + ni * 8 + grp;
                Bf[ni] = *reinterpret_cast<const uint4*>(Bs + c * GSTR + ko);
            }
#pragma unroll
            for (int mi = 0; mi < 4; mi++) {
                const int r = wm * 64 + mi * 16 + grp;
                uint4 Aa = *reinterpret_cast<const uint4*>(As + (r    ) * GSTR + ko);
                uint4 Ab = *reinterpret_cast<const uint4*>(As + (r + 8) * GSTR + ko);
#pragma unroll
                for (int ni = 0; ni < 4; ni++) {
                    mma_f16(acc[mi][ni][0], acc[mi][ni][1], acc[mi][ni][2], acc[mi][ni][3],
                            Aa.x, Ab.x, Aa.y, Ab.y, Bf[ni].x, Bf[ni].y);
                    mma_f16(acc[mi][ni][0], acc[mi][ni][1], acc[mi][ni][2], acc[mi][ni][3],
                            Aa.z, Ab.z, Aa.w, Ab.w, Bf[ni].z, Bf[ni].w);
                }
            }
        }
        __syncthreads();
        if (kt < 14) issue(kt & 1, (kt + 2) * 64);
        else cpa_commit();
    }

#pragma unroll
    for (int mi = 0; mi < 4; mi++) {
        const int r = m0 + wm * 64 + mi * 16 + grp;
#pragma unroll
        for (int ni = 0; ni < 4; ni++) {
            const int c = n0 + wn * 32 + ni * 8 + tg * 2;
            float2 bv = *reinterpret_cast<const float2*>(bias + c);
            float2 o0, o1;
            o0.x = acc[mi][ni][0] + bv.x;  o0.y = acc[mi][ni][1] + bv.y;
            o1.x = acc[mi][ni][2] + bv.x;  o1.y = acc[mi][ni][3] + bv.y;
            *reinterpret_cast<float2*>(C + (size_t)r * G4 + c)       = o0;
            *reinterpret_cast<float2*>(C + (size_t)(r + 8) * G4 + c) = o1;
        }
    }
}
#define GEMM_SMEM (4 * GSTAGE * (int)sizeof(__half))   // 96 KB

// ---------------- fused two-layer persistent recurrence (R10 config) --------------
// 128 CTAs x 256 threads, 8 warps = 2 M-halves x 4 K-slices (proven optimum).
// Round s (0..513):
//   PRE-WAIT : rc = carry partials (h0(s-2)@Wx1 from round s-1); xw(s) prefetch
//   WAIT(s)  : 128 threads ld.acquire one flag each + __syncthreads_and
//   MERGED   : X = h0(s-1), Y = h1(s-3), both depth-1 streamed (8 uint4/lane in
//              flight); one Bv(Wh) feeds acc0 (X@Wh) and acc1 (Y@Wh); Cv(Wx1)
//              feeds accC (X@Wx1). Spill acc0/acc1 fp32, accC fp16 carry.
//   EPILOGUE : h0(s), h1(s-2) stores -> flag -> deferred streaming seq/cdump
#define WT_STRIDE 1056              // halves
#define PS_STRIDE 36                // floats (Ps0/Ps1), halves (PsC)
#define WSLICE (32 * WT_STRIDE)     // halves per weight slice
#define PSLICE (4 * 64 * PS_STRIDE) // floats per fp32 partial buffer
#define SMEM_BYTES (2 * WSLICE * 2 + 2 * PSLICE * 4 + PSLICE * 2)   // 222 KB

__global__ void __launch_bounds__(NTHR, 1)
lstm_fused(const float* __restrict__ xw,
           __half* __restrict__ h0A, __half* __restrict__ h0B, __half* __restrict__ h0C,
           __half* __restrict__ h1A, __half* __restrict__ h1B,
           float* __restrict__ cdump, float* __restrict__ seq_out) {
    extern __shared__ __align__(16) unsigned char smem_raw[];
    __half* WhS  = reinterpret_cast<__half*>(smem_raw);              // [32][WT_STRIDE]
    __half* Wx1S = WhS + WSLICE;                                     // [32][WT_STRIDE]
    float*  Ps0  = reinterpret_cast<float*>(smem_raw + 2 * WSLICE * 2);
    float*  Ps1  = Ps0 + PSLICE;
    __half* PsC  = reinterpret_cast<__half*>(Ps1 + PSLICE);          // fp16 carry

    const int tid  = threadIdx.x;
    const int warp = tid >> 5, lane = tid & 31;
    const int grp  = lane >> 2, tg = lane & 3;
    const int wm = warp & 1;                 // M half (32 rows)
    const int ks = warp >> 1;                // K slice: [ks*256, +256)

    const int n0 = blockIdx.x * 32;          // packed gate column base
    const int J0 = blockIdx.x * 8;           // hidden-unit base

    const unsigned base = g_flags[blockIdx.x];

    // ---- preload weight slices ([n][kperm] fp16: raw vector copies) ----
    for (int idx = tid; idx < 32 * 128; idx += NTHR) {
        int c = idx >> 7, ch = idx & 127;
        *reinterpret_cast<uint4*>(WhS  + c * WT_STRIDE + ch * 8) =
            *reinterpret_cast<const uint4*>(g_Whh  + (size_t)(n0 + c) * KD + ch * 8);
        *reinterpret_cast<uint4*>(Wx1S + c * WT_STRIDE + ch * 8) =
            *reinterpret_cast<const uint4*>(g_Wx1h + (size_t)(n0 + c) * KD + ch * 8);
    }

    // ---- zero own h columns (all 5 buffers) + PsC ----
    for (int idx = tid; idx < 512; idx += NTHR) {
        int b = idx >> 3, j = idx & 7;
        int p = b * HDIM + hperm16(J0 + j);
        __half z = __float2half(0.0f);
        h0A[p] = z; h0B[p] = z; h0C[p] = z; h1A[p] = z; h1B[p] = z;
    }
    for (int idx = tid; idx < PSLICE / 2; idx += NTHR)
        reinterpret_cast<uint*>(PsC)[idx] = 0u;

    // ---- per-thread layer-1 bias ----
    float4 bs1[2];
#pragma unroll
    for (int it = 0; it < 2; it++) {
        int idx = tid + it * NTHR;
        int col = (idx & 7) << 2;
        bs1[it] = *reinterpret_cast<const float4*>(g_bias + n0 + col);
    }

    __syncthreads();
    if (tid == 0) st_rel(&g_flags[blockIdx.x], base + 1);

    float c0reg[2] = {0.0f, 0.0f};
    float c1reg[2] = {0.0f, 0.0f};
    __half* h0buf[3] = {h0A, h0B, h0C};
    __half* h1buf[2] = {h1A, h1B};

    const int r0 = wm * 32 + grp;
    const int kbase = ks * 256;
    const size_t laneoff = kbase + tg * 8;

    for (int s = 0; s <= SEQ + 1; s++) {
        // ---- PRE-WAIT: carry rc = h0(s-2)@Wx1 partials (own SMEM) ----
        float4 rc[2];
#pragma unroll
        for (int it = 0; it < 2; it++) {
            int idx = tid + it * NTHR;
            int b = idx >> 3, j = idx & 7;
            const __half* cb = PsC + b * PS_STRIDE + (j << 2);
            float4 rs = make_float4(0.f, 0.f, 0.f, 0.f);
#pragma unroll
            for (int k4 = 0; k4 < 4; k4++) {
                uint2 raw = *reinterpret_cast<const uint2*>(cb + k4 * 64 * PS_STRIDE);
                float2 f0 = __half22float2(*reinterpret_cast<__half2*>(&raw.x));
                float2 f1 = __half22float2(*reinterpret_cast<__half2*>(&raw.y));
                rs.x += f0.x; rs.y += f0.y; rs.z += f1.x; rs.w += f1.y;
            }
            rc[it] = rs;
        }

        // ---- prefetch xw(s) ----
        float4 xv[2];
        if (s < SEQ) {
            const float* xw_t = xw + (size_t)s * BS * G4;
#pragma unroll
            for (int it = 0; it < 2; it++) {
                int idx = tid + it * NTHR;
                int b = idx >> 3, col = (idx & 7) << 2;
                xv[it] = *reinterpret_cast<const float4*>(xw_t + (size_t)b * G4 + n0 + col);
            }
        }

        // ---- WAIT: all CTAs finished round s-1 ----
        {
            const unsigned target = base + 1 + (unsigned)s;
            bool ok;
            do {
                unsigned v = (tid < NCTA) ? ld_acq(&g_flags[tid]) : target;
                ok = (int)(v - target) >= 0;
            } while (!__syncthreads_and(ok));
        }

        // ---- MERGED phase: X = h0(s-1), Y = h1(s-3), both depth-1 ----
        {
            const __half* xr = h0buf[(s + 2) % 3];
            const __half* yr = h1buf[(s + 1) & 1];
            const __half* xp0 = xr + (size_t)(r0      ) * KD + laneoff;
            const __half* xp1 = xr + (size_t)(r0 +  8) * KD + laneoff;
            const __half* xp2 = xr + (size_t)(r0 + 16) * KD + laneoff;
            const __half* xp3 = xr + (size_t)(r0 + 24) * KD + laneoff;
            const __half* yp0 = yr + (size_t)(r0      ) * KD + laneoff;
            const __half* yp1 = yr + (size_t)(r0 +  8) * KD + laneoff;
            const __half* yp2 = yr + (size_t)(r0 + 16) * KD + laneoff;
            const __half* yp3 = yr + (size_t)(r0 + 24) * KD + laneoff;

            float acc0[2][4][4], acc1[2][4][4], accC[2][4][4];
#pragma unroll
            for (int mt = 0; mt < 2; mt++)
#pragma unroll
                for (int nt = 0; nt < 4; nt++)
#pragma unroll
                    for (int q = 0; q < 4; q++) {
                        acc0[mt][nt][q] = 0.0f; acc1[mt][nt][q] = 0.0f; accC[mt][nt][q] = 0.0f;
                    }

            uint4 X0 = *reinterpret_cast<const uint4*>(xp0);
            uint4 X1 = *reinterpret_cast<const uint4*>(xp1);
            uint4 X2 = *reinterpret_cast<const uint4*>(xp2);
            uint4 X3 = *reinterpret_cast<const uint4*>(xp3);
            uint4 Y0 = *reinterpret_cast<const uint4*>(yp0);
            uint4 Y1 = *reinterpret_cast<const uint4*>(yp1);
            uint4 Y2 = *reinterpret_cast<const uint4*>(yp2);
            uint4 Y3 = *reinterpret_cast<const uint4*>(yp3);

#pragma unroll
            for (int g = 0; g < 8; g++) {
                uint4 NX0, NX1, NX2, NX3, NY0, NY1, NY2, NY3;
                if (g < 7) {
                    const int off = (g + 1) * 32;
                    NX0 = *reinterpret_cast<const uint4*>(xp0 + off);
                    NX1 = *reinterpret_cast<const uint4*>(xp1 + off);
                    NX2 = *reinterpret_cast<const uint4*>(xp2 + off);
                    NX3 = *reinterpret_cast<const uint4*>(xp3 + off);
                    NY0 = *reinterpret_cast<const uint4*>(yp0 + off);
                    NY1 = *reinterpret_cast<const uint4*>(yp1 + off);
                    NY2 = *reinterpret_cast<const uint4*>(yp2 + off);
                    NY3 = *reinterpret_cast<const uint4*>(yp3 + off);
                }
#pragma unroll
                for (int nt = 0; nt < 4; nt++) {
                    const int c = nt * 8 + grp;
                    uint4 Bv = *reinterpret_cast<const uint4*>(
                        WhS + c * WT_STRIDE + kbase + g * 32 + tg * 8);
                    uint4 Cv = *reinterpret_cast<const uint4*>(
                        Wx1S + c * WT_STRIDE + kbase + g * 32 + tg * 8);
                    // acc0 = X @ Wh
                    mma_f16(acc0[0][nt][0], acc0[0][nt][1], acc0[0][nt][2], acc0[0][nt][3],
                            X0.x, X1.x, X0.y, X1.y, Bv.x, Bv.y);
                    mma_f16(acc0[1][nt][0], acc0[1][nt][1], acc0[1][nt][2], acc0[1][nt][3],
                            X2.x, X3.x, X2.y, X3.y, Bv.x, Bv.y);
                    mma_f16(acc0[0][nt][0], acc0[0][nt][1], acc0[0][nt][2], acc0[0][nt][3],
                            X0.z, X1.z, X0.w, X1.w, Bv.z, Bv.w);
                    mma_f16(acc0[1][nt][0], acc0[1][nt][1], acc0[1][nt][2], acc0[1][nt][3],
                            X2.z, X3.z, X2.w, X3.w, Bv.z, Bv.w);
                    // acc1 = Y @ Wh (same Bv)
                    mma_f16(acc1[0][nt][0], acc1[0][nt][1], acc1[0][nt][2], acc1[0][nt][3],
                            Y0.x, Y1.x, Y0.y, Y1.y, Bv.x, Bv.y);
                    mma_f16(acc1[1][nt][0], acc1[1][nt][1], acc1[1][nt][2], acc1[1][nt][3],
                            Y2.x, Y3.x, Y2.y, Y3.y, Bv.x, Bv.y);
                    mma_f16(acc1[0][nt][0], acc1[0][nt][1], acc1[0][nt][2], acc1[0][nt][3],
                            Y0.z, Y1.z, Y0.w, Y1.w, Bv.z, Bv.w);
                    mma_f16(acc1[1][nt][0], acc1[1][nt][1], acc1[1][nt][2], acc1[1][nt][3],
                            Y2.z, Y3.z, Y2.w, Y3.w, Bv.z, Bv.w);
                    // accC = X @ Wx1
                    mma_f16(accC[0][nt][0], accC[0][nt][1], accC[0][nt][2], accC[0][nt][3],
                            X0.x, X1.x, X0.y, X1.y, Cv.x, Cv.y);
                    mma_f16(accC[1][nt][0], accC[1][nt][1], accC[1][nt][2], accC[1][nt][3],
                            X2.x, X3.x, X2.y, X3.y, Cv.x, Cv.y);
                    mma_f16(accC[0][nt][0], accC[0][nt][1], accC[0][nt][2], accC[0][nt][3],
                            X0.z, X1.z, X0.w, X1.w, Cv.z, Cv.w);
                    mma_f16(accC[1][nt][0], accC[1][nt][1], accC[1][nt][2], accC[1][nt][3],
                            X2.z, X3.z, X2.w, X3.w, Cv.z, Cv.w);
                }
                X0 = NX0; X1 = NX1; X2 = NX2; X3 = NX3;
                Y0 = NY0; Y1 = NY1; Y2 = NY2; Y3 = NY3;
            }

            // spill: acc0/acc1 fp32, accC fp16 carry for round s+1
            float*  P0s = Ps0 + ks * 64 * PS_STRIDE;
            float*  P1s = Ps1 + ks * 64 * PS_STRIDE;
            __half* PCs = PsC + ks * 64 * PS_STRIDE;
#pragma unroll
            for (int mt = 0; mt < 2; mt++) {
                const int r = wm * 32 + mt * 16 + grp;
#pragma unroll
                for (int nt = 0; nt < 4; nt++) {
                    const int c = nt * 8 + tg * 2;
                    *reinterpret_cast<float2*>(P0s + (r    ) * PS_STRIDE + c) =
                        make_float2(acc0[mt][nt][0], acc0[mt][nt][1]);
                    *reinterpret_cast<float2*>(P0s + (r + 8) * PS_STRIDE + c) =
                        make_float2(acc0[mt][nt][2], acc0[mt][nt][3]);
                    *reinterpret_cast<float2*>(P1s + (r    ) * PS_STRIDE + c) =
                        make_float2(acc1[mt][nt][0], acc1[mt][nt][1]);
                    *reinterpret_cast<float2*>(P1s + (r + 8) * PS_STRIDE + c) =
                        make_float2(acc1[mt][nt][2], acc1[mt][nt][3]);
                    *reinterpret_cast<__half2*>(PCs + (r    ) * PS_STRIDE + c) =
                        __floats2half2_rn(accC[mt][nt][0], accC[mt][nt][1]);
                    *reinterpret_cast<__half2*>(PCs + (r + 8) * PS_STRIDE + c) =
                        __floats2half2_rn(accC[mt][nt][2], accC[mt][nt][3]);
                }
            }
        }
        __syncthreads();

        // ---- epilogue rec0: h0(s) (critical-path store) ----
        if (s < SEQ) {
            __half* hw = h0buf[s % 3];
#pragma unroll
            for (int it = 0; it < 2; it++) {
                int idx = tid + it * NTHR;
                int b = idx >> 3, j = idx & 7;
                int col = j << 2;
                float4 p0 = *reinterpret_cast<const float4*>(Ps0 + 0 * 64 * PS_STRIDE + b * PS_STRIDE + col);
                float4 p1 = *reinterpret_cast<const float4*>(Ps0 + 1 * 64 * PS_STRIDE + b * PS_STRIDE + col);
                float4 p2 = *reinterpret_cast<const float4*>(Ps0 + 2 * 64 * PS_STRIDE + b * PS_STRIDE + col);
                float4 p3 = *reinterpret_cast<const float4*>(Ps0 + 3 * 64 * PS_STRIDE + b * PS_STRIDE + col);

                float pi  = xv[it].x + ((p0.x + p1.x) + (p2.x + p3.x));
                float pfv = xv[it].y + ((p0.y + p1.y) + (p2.y + p3.y));
                float pg  = xv[it].z + ((p0.z + p1.z) + (p2.z + p3.z));
                float po  = xv[it].w + ((p0.w + p1.w) + (p2.w + p3.w));

                float gi = sigmoidf_(pi);
                float gf = sigmoidf_(pfv);
                float gg = tanhfast(pg);
                float go = sigmoidf_(po);

                float cv = gf * c0reg[it] + gi * gg;
                c0reg[it] = cv;
                float hv = go * tanhfast(cv);
                hw[b * HDIM + hperm16(J0 + j)] = __float2half(hv);
            }
        }

        // ---- epilogue rec1: h1(s-2) (critical store); seq/cdump deferred ----
        float hv1[2]; float cv1[2];
        if (s >= 2) {
            __half* hw = h1buf[s & 1];
#pragma unroll
            for (int it = 0; it < 2; it++) {
                int idx = tid + it * NTHR;
                int b = idx >> 3, j = idx & 7;
                int col = j << 2;
                float4 p0 = *reinterpret_cast<const float4*>(Ps1 + 0 * 64 * PS_STRIDE + b * PS_STRIDE + col);
                float4 p1 = *reinterpret_cast<const float4*>(Ps1 + 1 * 64 * PS_STRIDE + b * PS_STRIDE + col);
                float4 p2 = *reinterpret_cast<const float4*>(Ps1 + 2 * 64 * PS_STRIDE + b * PS_STRIDE + col);
                float4 p3 = *reinterpret_cast<const float4*>(Ps1 + 3 * 64 * PS_STRIDE + b * PS_STRIDE + col);

                float pi  = bs1[it].x + rc[it].x + ((p0.x + p1.x) + (p2.x + p3.x));
                float pfv = bs1[it].y + rc[it].y + ((p0.y + p1.y) + (p2.y + p3.y));
                float pg  = bs1[it].z + rc[it].z + ((p0.z + p1.z) + (p2.z + p3.z));
                float po  = bs1[it].w + rc[it].w + ((p0.w + p1.w) + (p2.w + p3.w));

                float gi = sigmoidf_(pi);
                float gf = sigmoidf_(pfv);
                float gg = tanhfast(pg);
                float go = sigmoidf_(po);

                float cv = gf * c1reg[it] + gi * gg;
                c1reg[it] = cv;
                float hv = go * tanhfast(cv);
                cv1[it] = cv; hv1[it] = hv;

                int J = J0 + j;
                hw[b * HDIM + hperm16(J)] = __float2half(hv);
            }
        }

        __syncthreads();
        if (tid == 0) st_rel(&g_flags[blockIdx.x], base + 2 + (unsigned)s);

        // ---- deferred non-critical stores (after flag release, streaming) ----
        if (s >= 2) {
            float* so = seq_out + (size_t)(s - 2) * BS * HDIM;
#pragma unroll
            for (int it = 0; it < 2; it++) {
                int idx = tid + it * NTHR;
                int b = idx >> 3, j = idx & 7;
                int J = J0 + j;
                __stcs(so + (size_t)b * HDIM + J, hv1[it]);     // write-once: bypass L2 residency
                if (s == SEQ + 1) __stcs(cdump + b * HDIM + J, cv1[it]);
            }
        }
    }
}

// ---------------- tail: (h, c) after the sequence --------------------------------
__global__ void copy_tail(const float* __restrict__ hsrc, const float* __restrict__ csrc,
                          float* __restrict__ dst) {
    int i = blockIdx.x * blockDim.x + threadIdx.x;
    if (i < BS * HDIM) {
        dst[i] = hsrc[i];
        dst[BS * HDIM + i] = csrc[i];
    }
}

// ---------------- launcher --------------------------------------------------------
extern "C" void kernel_launch(void* const* d_in, const int* in_sizes, int n_in,
                              void* d_out, int out_size) {
    (void)in_sizes; (void)n_in;

    const float* x     = (const float*)d_in[0];
    const float* Wii0  = (const float*)d_in[1];
    const float* Wii   = (const float*)d_in[2];
    const float* Whi   = (const float*)d_in[3];
    const float* Wif0  = (const float*)d_in[4];
    const float* Wif   = (const float*)d_in[5];
    const float* Whf   = (const float*)d_in[6];
    const float* Wig0  = (const float*)d_in[7];
    const float* Wig   = (const float*)d_in[8];
    const float* Whg   = (const float*)d_in[9];
    const float* Wio0  = (const float*)d_in[10];
    const float* Wio   = (const float*)d_in[11];
    const float* Who   = (const float*)d_in[12];
    const float* bi    = (const float*)d_in[13];
    const float* bf    = (const float*)d_in[14];
    const float* bg    = (const float*)d_in[15];
    const float* bo    = (const float*)d_in[16];

    float *pBias, *pXw, *pC;
    __half *pWx0h, *pWx1h, *pWhh, *pAh, *pH0A, *pH0B, *pH0C, *pH1A, *pH1B;
    cudaGetSymbolAddress((void**)&pWx0h, g_Wx0h);
    cudaGetSymbolAddress((void**)&pWx1h, g_Wx1h);
    cudaGetSymbolAddress((void**)&pWhh,  g_Whh);
    cudaGetSymbolAddress((void**)&pBias, g_bias);
    cudaGetSymbolAddress((void**)&pXw,   g_xw);
    cudaGetSymbolAddress((void**)&pAh,   g_Ah);
    cudaGetSymbolAddress((void**)&pH0A,  g_h0A);
    cudaGetSymbolAddress((void**)&pH0B,  g_h0B);
    cudaGetSymbolAddress((void**)&pH0C,  g_h0C);
    cudaGetSymbolAddress((void**)&pH1A,  g_h1A);
    cudaGetSymbolAddress((void**)&pH1B,  g_h1B);
    cudaGetSymbolAddress((void**)&pC,    g_c);

    float* out = (float*)d_out;

    static bool attr_set = false;
    if (!attr_set) {
        cudaFuncSetAttribute(lstm_fused,
                             cudaFuncAttributeMaxDynamicSharedMemorySize, SMEM_BYTES);
        cudaFuncSetAttribute(gemm_xw_f16,
                             cudaFuncAttributeMaxDynamicSharedMemorySize, GEMM_SMEM);
        attr_set = true;
    }

    // launch order: pack_all, cvtA, gemm0, lstm_fused (4th = ncu-profiled)
    pack_all<<<3073, 256>>>(Wii0, Wif0, Wig0, Wio0,
                            Wii,  Wif,  Wig,  Wio,
                            Whi,  Whf,  Whg,  Who,
                            bi, bf, bg, bo,
                            pWx0h, pWx1h, pWhh, pBias);
    {
        int n = SEQ * BS * IN_DIM;
        cvtA<<<(n / 2 + 255) / 256, 256>>>(x, pAh, n);
    }

    const dim3 gemm_grid(G4 / 128, (SEQ * BS) / 128);  // (32, 256)
    gemm_xw_f16<<<gemm_grid, 256, GEMM_SMEM>>>(pAh, pWx0h, pXw, pBias);

    lstm_fused<<<NCTA, NTHR, SMEM_BYTES>>>(pXw, pH0A, pH0B, pH0C, pH1A, pH1B, pC, out);

    // tail: final (h, c) of layer 1. h final = seq output at t = SEQ-1.
    size_t seqN = (size_t)SEQ * BS * HDIM;
    if ((size_t)out_size >= seqN + 2 * (size_t)BS * HDIM) {
        copy_tail<<<(BS * HDIM + 255) / 256, 256>>>(out + seqN - (size_t)BS * HDIM,
                                                    pC, out + seqN);
    }
}

// round 14
// speedup vs baseline: 2.3608x; 1.0841x over previous
#include <cuda_runtime.h>
#include <cuda_fp16.h>
#include <cstdint>

#define SEQ 512
#define BS 64
#define IN_DIM 1024
#define HDIM 1024
#define G4 4096           // 4 gates * H, packed as [k][j*4 + gate]
#define KD 1024
#define NCTA 128
#define NTHR 256

// ---------------- device scratch (allocation rules forbid cudaMalloc) -----------
__device__ __half g_Wx0h[(size_t)G4 * KD];        // layer0 input W, [n][kperm] fp16
__device__ __half g_Wx1h[(size_t)G4 * KD];        // layer1 input W, [n][kperm] fp16
__device__ __half g_Whh [(size_t)G4 * KD];        // recurrent W,   [n][kperm] fp16
__device__ float  g_bias[G4];
__device__ __half g_xw [(size_t)SEQ * BS * G4];   // X@Wx0 + b (layer 0), fp16
__device__ __half g_Ah [(size_t)SEQ * BS * KD];   // GEMM A, fp16 [m][kperm]
__device__ __half g_h0A[BS * HDIM];               // layer0 h ring-of-3 (fp16 perm)
__device__ __half g_h0B[BS * HDIM];
__device__ __half g_h0C[BS * HDIM];
__device__ __half g_h1A[BS * HDIM];               // layer1 h ring-of-2 (fp16 perm)
__device__ __half g_h1B[BS * HDIM];
__device__ float  g_c [BS * HDIM];

// monotonic per-CTA step flags (graph-replay safe: base re-read each launch)
__device__ __align__(16) unsigned g_flags[NCTA];

// ---------------- helpers -------------------------------------------------------
__device__ __forceinline__ void mma_f16(float& c0, float& c1, float& c2, float& c3,
                                        unsigned a0, unsigned a1, unsigned a2, unsigned a3,
                                        unsigned b0, unsigned b1) {
    asm volatile(
        "mma.sync.aligned.m16n8k16.row.col.f32.f16.f16.f32 "
        "{%0,%1,%2,%3}, {%4,%5,%6,%7}, {%8,%9}, {%0,%1,%2,%3};"
        : "+f"(c0), "+f"(c1), "+f"(c2), "+f"(c3)
        : "r"(a0), "r"(a1), "r"(a2), "r"(a3), "r"(b0), "r"(b1));
}

__device__ __forceinline__ float tanhfast(float x) {
    float y; asm("tanh.approx.f32 %0, %1;" : "=f"(y) : "f"(x)); return y;
}
__device__ __forceinline__ float sigmoidf_(float x) {
    return fmaf(tanhfast(0.5f * x), 0.5f, 0.5f);   // 1 MUFU instead of EX2+RCP
}

__device__ __forceinline__ unsigned ld_acq(const unsigned* p) {
    unsigned v;
    asm volatile("ld.acquire.gpu.global.u32 %0, [%1];" : "=r"(v) : "l"(p) : "memory");
    return v;
}
__device__ __forceinline__ void st_rel(unsigned* p, unsigned v) {
    asm volatile("st.release.gpu.global.u32 [%0], %1;" :: "l"(p), "r"(v) : "memory");
}

__device__ __forceinline__ void cpa16(void* s, const void* g) {
    unsigned sa = (unsigned)__cvta_generic_to_shared(s);
    asm volatile("cp.async.cg.shared.global [%0], [%1], 16;" :: "r"(sa), "l"(g));
}
__device__ __forceinline__ void cpa_commit() {
    asm volatile("cp.async.commit_group;");
}
__device__ __forceinline__ void cpa_wait1() {
    asm volatile("cp.async.wait_group 1;");
}

// fp16 k-permutation within each 32-k block
__device__ __host__ __forceinline__ int hperm16(int k) {
    int t = k & 31;
    int tile = t >> 4;
    int u = t & 15;
    int b = u & 1;
    int tg = (u >> 1) & 3;
    int c = u >> 3;
    return (k & ~31) | (tg * 8 + tile * 4 + c * 2 + b);
}

// ---------------- fused packing kernel --------------------------------------------
__global__ void pack_all(
    const float* __restrict__ Wi0, const float* __restrict__ Wf0,
    const float* __restrict__ Wg0, const float* __restrict__ Wo0,
    const float* __restrict__ Wi1, const float* __restrict__ Wf1,
    const float* __restrict__ Wg1, const float* __restrict__ Wo1,
    const float* __restrict__ Whi, const float* __restrict__ Whf,
    const float* __restrict__ Whg, const float* __restrict__ Who,
    const float* __restrict__ bi,  const float* __restrict__ bf,
    const float* __restrict__ bg,  const float* __restrict__ bo,
    __half* __restrict__ Wx0h, __half* __restrict__ Wx1h,
    __half* __restrict__ Whh, float* __restrict__ bias) {
    const int bid = blockIdx.x;
    const int tid = threadIdx.x;
    if (bid < 3072) {
        const int set = bid >> 10;
        const int rem = bid & 1023;
        const int gate = rem >> 8;
        const int tile = rem & 255;
        const float* W;
        __half* dst;
        if (set == 0) {
            W = (gate == 0) ? Wi0 : (gate == 1) ? Wf0 : (gate == 2) ? Wg0 : Wo0;
            dst = Wx0h;
        } else if (set == 1) {
            W = (gate == 0) ? Wi1 : (gate == 1) ? Wf1 : (gate == 2) ? Wg1 : Wo1;
            dst = Wx1h;
        } else {
            W = (gate == 0) ? Whi : (gate == 1) ? Whf : (gate == 2) ? Whg : Who;
            dst = Whh;
        }
        const int k0 = (tile & 15) * 64, j0 = (tile >> 4) * 64;
        __shared__ __half t[64][65];
#pragma unroll
        for (int it = 0; it < 16; it++) {
            int v = tid + it * 256;
            int ky = v >> 6, jx = v & 63;
            t[ky][jx] = __float2half(W[(size_t)(k0 + ky) * HDIM + j0 + jx]);
        }
        __syncthreads();
#pragma unroll
        for (int it = 0; it < 16; it++) {
            int v = tid + it * 256;
            int jy = v >> 6, kx = v & 63;
            int n = (j0 + jy) * 4 + gate;
            dst[(size_t)n * KD + hperm16(k0 + kx)] = t[kx][jy];
        }
    } else {
#pragma unroll
        for (int e = 0; e < 4; e++) {
            int j = tid + e * 256;
            float4 v;
            v.x = bi[j]; v.y = bf[j]; v.z = bg[j]; v.w = bo[j];
            reinterpret_cast<float4*>(bias)[j] = v;
        }
    }
}

// A conversion: fp32 [m][k] -> fp16 [m][hperm16(k)]
__global__ void cvtA(const float* __restrict__ src, __half* __restrict__ dst, int total) {
    int i2 = blockIdx.x * blockDim.x + threadIdx.x;
    int idx = i2 * 2;
    if (idx >= total) return;
    float2 v = *reinterpret_cast<const float2*>(src + idx);
    int m = idx >> 10, k = idx & 1023;
    *reinterpret_cast<__half2*>(dst + ((size_t)m << 10) + hperm16(k)) =
        __floats2half2_rn(v.x, v.y);
}

// ---------------- big input-projection GEMM (fp16, cp.async 2-stage) -------------
// Output now fp16 (xw buffer).
#define GSTR 96
#define GSTAGE (128 * GSTR)

__global__ void __launch_bounds__(256, 2)
gemm_xw_f16(const __half* __restrict__ A, const __half* __restrict__ B,
            __half* __restrict__ C, const float* __restrict__ bias) {
    extern __shared__ __align__(16) __half gs[];
    const int m0 = blockIdx.y * 128;
    const int n0 = blockIdx.x * 128;
    const int tid  = threadIdx.x;
    const int warp = tid >> 5, lane = tid & 31;
    const int grp  = lane >> 2, tg = lane & 3;
    const int wm = warp & 1;
    const int wn = warp >> 1;

    const int cc = tid & 7;
    const int rr = tid >> 3;

    auto issue = [&](int st, int kofs) {
        __half* As = gs + st * GSTAGE;
        __half* Bs = gs + 2 * GSTAGE + st * GSTAGE;
#pragma unroll
        for (int i = 0; i < 4; i++) {
            int row = rr + i * 32;
            cpa16(As + row * GSTR + cc * 8,
                  A + (size_t)(m0 + row) * KD + kofs + cc * 8);
            cpa16(Bs + row * GSTR + cc * 8,
                  B + (size_t)(n0 + row) * KD + kofs + cc * 8);
        }
        cpa_commit();
    };

    issue(0, 0);
    issue(1, 64);

    float acc[4][4][4];
#pragma unroll
    for (int mi = 0; mi < 4; mi++)
#pragma unroll
        for (int ni = 0; ni < 4; ni++)
#pragma unroll
            for (int q = 0; q < 4; q++) acc[mi][ni][q] = 0.0f;

    for (int kt = 0; kt < 16; kt++) {
        cpa_wait1();
        __syncthreads();
        const __half* As = gs + (kt & 1) * GSTAGE;
        const __half* Bs = gs + 2 * GSTAGE + (kt & 1) * GSTAGE;

#pragma unroll
        for (int g32 = 0; g32 < 2; g32++) {
            const int ko = g32 * 32 + tg * 8;
            uint4 Bf[4];
#pragma unroll
            for (int ni = 0; ni < 4; ni++) {
                const int c = wn * 32 + ni * 8 + grp;
                Bf[ni] = *reinterpret_cast<const uint4*>(Bs + c * GSTR + ko);
            }
#pragma unroll
            for (int mi = 0; mi < 4; mi++) {
                const int r = wm * 64 + mi * 16 + grp;
                uint4 Aa = *reinterpret_cast<const uint4*>(As + (r    ) * GSTR + ko);
                uint4 Ab = *reinterpret_cast<const uint4*>(As + (r + 8) * GSTR + ko);
#pragma unroll
                for (int ni = 0; ni < 4; ni++) {
                    mma_f16(acc[mi][ni][0], acc[mi][ni][1], acc[mi][ni][2], acc[mi][ni][3],
                            Aa.x, Ab.x, Aa.y, Ab.y, Bf[ni].x, Bf[ni].y);
                    mma_f16(acc[mi][ni][0], acc[mi][ni][1], acc[mi][ni][2], acc[mi][ni][3],
                            Aa.z, Ab.z, Aa.w, Ab.w, Bf[ni].z, Bf[ni].w);
                }
            }
        }
        __syncthreads();
        if (kt < 14) issue(kt & 1, (kt + 2) * 64);
        else cpa_commit();
    }

#pragma unroll
    for (int mi = 0; mi < 4; mi++) {
        const int r = m0 + wm * 64 + mi * 16 + grp;
#pragma unroll
        for (int ni = 0; ni < 4; ni++) {
            const int c = n0 + wn * 32 + ni * 8 + tg * 2;
            float2 bv = *reinterpret_cast<const float2*>(bias + c);
            __half2 o0 = __floats2half2_rn(acc[mi][ni][0] + bv.x, acc[mi][ni][1] + bv.y);
            __half2 o1 = __floats2half2_rn(acc[mi][ni][2] + bv.x, acc[mi][ni][3] + bv.y);
            *reinterpret_cast<__half2*>(C + (size_t)r * G4 + c)       = o0;
            *reinterpret_cast<__half2*>(C + (size_t)(r + 8) * G4 + c) = o1;
        }
    }
}
#define GEMM_SMEM (4 * GSTAGE * (int)sizeof(__half))   // 96 KB

// ---------------- fused two-layer persistent recurrence (R10/R13 config) ----------
#define WT_STRIDE 1056              // halves
#define PS_STRIDE 36                // floats (Ps0/Ps1), halves (PsC)
#define WSLICE (32 * WT_STRIDE)     // halves per weight slice
#define PSLICE (4 * 64 * PS_STRIDE) // floats per fp32 partial buffer
#define SMEM_BYTES (2 * WSLICE * 2 + 2 * PSLICE * 4 + PSLICE * 2)   // 222 KB

__global__ void __launch_bounds__(NTHR, 1)
lstm_fused(const __half* __restrict__ xw,
           __half* __restrict__ h0A, __half* __restrict__ h0B, __half* __restrict__ h0C,
           __half* __restrict__ h1A, __half* __restrict__ h1B,
           float* __restrict__ cdump, float* __restrict__ seq_out) {
    extern __shared__ __align__(16) unsigned char smem_raw[];
    __half* WhS  = reinterpret_cast<__half*>(smem_raw);              // [32][WT_STRIDE]
    __half* Wx1S = WhS + WSLICE;                                     // [32][WT_STRIDE]
    float*  Ps0  = reinterpret_cast<float*>(smem_raw + 2 * WSLICE * 2);
    float*  Ps1  = Ps0 + PSLICE;
    __half* PsC  = reinterpret_cast<__half*>(Ps1 + PSLICE);          // fp16 carry

    const int tid  = threadIdx.x;
    const int warp = tid >> 5, lane = tid & 31;
    const int grp  = lane >> 2, tg = lane & 3;
    const int wm = warp & 1;                 // M half (32 rows)
    const int ks = warp >> 1;                // K slice: [ks*256, +256)

    const int n0 = blockIdx.x * 32;          // packed gate column base
    const int J0 = blockIdx.x * 8;           // hidden-unit base

    const unsigned base = g_flags[blockIdx.x];

    // ---- preload weight slices ([n][kperm] fp16: raw vector copies) ----
    for (int idx = tid; idx < 32 * 128; idx += NTHR) {
        int c = idx >> 7, ch = idx & 127;
        *reinterpret_cast<uint4*>(WhS  + c * WT_STRIDE + ch * 8) =
            *reinterpret_cast<const uint4*>(g_Whh  + (size_t)(n0 + c) * KD + ch * 8);
        *reinterpret_cast<uint4*>(Wx1S + c * WT_STRIDE + ch * 8) =
            *reinterpret_cast<const uint4*>(g_Wx1h + (size_t)(n0 + c) * KD + ch * 8);
    }

    // ---- zero own h columns (all 5 buffers) + PsC ----
    for (int idx = tid; idx < 512; idx += NTHR) {
        int b = idx >> 3, j = idx & 7;
        int p = b * HDIM + hperm16(J0 + j);
        __half z = __float2half(0.0f);
        h0A[p] = z; h0B[p] = z; h0C[p] = z; h1A[p] = z; h1B[p] = z;
    }
    for (int idx = tid; idx < PSLICE / 2; idx += NTHR)
        reinterpret_cast<uint*>(PsC)[idx] = 0u;

    // ---- per-thread layer-1 bias ----
    float4 bs1[2];
#pragma unroll
    for (int it = 0; it < 2; it++) {
        int idx = tid + it * NTHR;
        int col = (idx & 7) << 2;
        bs1[it] = *reinterpret_cast<const float4*>(g_bias + n0 + col);
    }

    __syncthreads();
    if (tid == 0) st_rel(&g_flags[blockIdx.x], base + 1);

    float c0reg[2] = {0.0f, 0.0f};
    float c1reg[2] = {0.0f, 0.0f};
    __half* h0buf[3] = {h0A, h0B, h0C};
    __half* h1buf[2] = {h1A, h1B};

    const int r0 = wm * 32 + grp;
    const int kbase = ks * 256;
    const size_t laneoff = kbase + tg * 8;

    for (int s = 0; s <= SEQ + 1; s++) {
        // ---- PRE-WAIT: carry rc = h0(s-2)@Wx1 partials (own SMEM) ----
        float4 rc[2];
#pragma unroll
        for (int it = 0; it < 2; it++) {
            int idx = tid + it * NTHR;
            int b = idx >> 3, j = idx & 7;
            const __half* cb = PsC + b * PS_STRIDE + (j << 2);
            float4 rs = make_float4(0.f, 0.f, 0.f, 0.f);
#pragma unroll
            for (int k4 = 0; k4 < 4; k4++) {
                uint2 raw = *reinterpret_cast<const uint2*>(cb + k4 * 64 * PS_STRIDE);
                float2 f0 = __half22float2(*reinterpret_cast<__half2*>(&raw.x));
                float2 f1 = __half22float2(*reinterpret_cast<__half2*>(&raw.y));
                rs.x += f0.x; rs.y += f0.y; rs.z += f1.x; rs.w += f1.y;
            }
            rc[it] = rs;
        }

        // ---- prefetch xw(s) (fp16, streaming: evict-first) ----
        float4 xv[2];
        if (s < SEQ) {
            const __half* xw_t = xw + (size_t)s * BS * G4;
#pragma unroll
            for (int it = 0; it < 2; it++) {
                int idx = tid + it * NTHR;
                int b = idx >> 3, col = (idx & 7) << 2;
                uint2 raw = __ldcs(reinterpret_cast<const uint2*>(
                    xw_t + (size_t)b * G4 + n0 + col));
                float2 f0 = __half22float2(*reinterpret_cast<__half2*>(&raw.x));
                float2 f1 = __half22float2(*reinterpret_cast<__half2*>(&raw.y));
                xv[it] = make_float4(f0.x, f0.y, f1.x, f1.y);
            }
        }

        // ---- WAIT: all CTAs finished round s-1 ----
        {
            const unsigned target = base + 1 + (unsigned)s;
            bool ok;
            do {
                unsigned v = (tid < NCTA) ? ld_acq(&g_flags[tid]) : target;
                ok = (int)(v - target) >= 0;
            } while (!__syncthreads_and(ok));
        }

        // ---- MERGED phase: X = h0(s-1), Y = h1(s-3), both depth-1 ----
        {
            const __half* xr = h0buf[(s + 2) % 3];
            const __half* yr = h1buf[(s + 1) & 1];
            const __half* xp0 = xr + (size_t)(r0      ) * KD + laneoff;
            const __half* xp1 = xr + (size_t)(r0 +  8) * KD + laneoff;
            const __half* xp2 = xr + (size_t)(r0 + 16) * KD + laneoff;
            const __half* xp3 = xr + (size_t)(r0 + 24) * KD + laneoff;
            const __half* yp0 = yr + (size_t)(r0      ) * KD + laneoff;
            const __half* yp1 = yr + (size_t)(r0 +  8) * KD + laneoff;
            const __half* yp2 = yr + (size_t)(r0 + 16) * KD + laneoff;
            const __half* yp3 = yr + (size_t)(r0 + 24) * KD + laneoff;

            float acc0[2][4][4], acc1[2][4][4], accC[2][4][4];
#pragma unroll
            for (int mt = 0; mt < 2; mt++)
#pragma unroll
                for (int nt = 0; nt < 4; nt++)
#pragma unroll
                    for (int q = 0; q < 4; q++) {
                        acc0[mt][nt][q] = 0.0f; acc1[mt][nt][q] = 0.0f; accC[mt][nt][q] = 0.0f;
                    }

            uint4 X0 = *reinterpret_cast<const uint4*>(xp0);
            uint4 X1 = *reinterpret_cast<const uint4*>(xp1);
            uint4 X2 = *reinterpret_cast<const uint4*>(xp2);
            uint4 X3 = *reinterpret_cast<const uint4*>(xp3);
            uint4 Y0 = *reinterpret_cast<const uint4*>(yp0);
            uint4 Y1 = *reinterpret_cast<const uint4*>(yp1);
            uint4 Y2 = *reinterpret_cast<const uint4*>(yp2);
            uint4 Y3 = *reinterpret_cast<const uint4*>(yp3);

#pragma unroll
            for (int g = 0; g < 8; g++) {
                uint4 NX0, NX1, NX2, NX3, NY0, NY1, NY2, NY3;
                if (g < 7) {
                    const int off = (g + 1) * 32;
                    NX0 = *reinterpret_cast<const uint4*>(xp0 + off);
                    NX1 = *reinterpret_cast<const uint4*>(xp1 + off);
                    NX2 = *reinterpret_cast<const uint4*>(xp2 + off);
                    NX3 = *reinterpret_cast<const uint4*>(xp3 + off);
                    NY0 = *reinterpret_cast<const uint4*>(yp0 + off);
                    NY1 = *reinterpret_cast<const uint4*>(yp1 + off);
                    NY2 = *reinterpret_cast<const uint4*>(yp2 + off);
                    NY3 = *reinterpret_cast<const uint4*>(yp3 + off);
                }
#pragma unroll
                for (int nt = 0; nt < 4; nt++) {
                    const int c = nt * 8 + grp;
                    uint4 Bv = *reinterpret_cast<const uint4*>(
                        WhS + c * WT_STRIDE + kbase + g * 32 + tg * 8);
                    uint4 Cv = *reinterpret_cast<const uint4*>(
                        Wx1S + c * WT_STRIDE + kbase + g * 32 + tg * 8);
                    // acc0 = X @ Wh
                    mma_f16(acc0[0][nt][0], acc0[0][nt][1], acc0[0][nt][2], acc0[0][nt][3],
                            X0.x, X1.x, X0.y, X1.y, Bv.x, Bv.y);
                    mma_f16(acc0[1][nt][0], acc0[1][nt][1], acc0[1][nt][2], acc0[1][nt][3],
                            X2.x, X3.x, X2.y, X3.y, Bv.x, Bv.y);
                    mma_f16(acc0[0][nt][0], acc0[0][nt][1], acc0[0][nt][2], acc0[0][nt][3],
                            X0.z, X1.z, X0.w, X1.w, Bv.z, Bv.w);
                    mma_f16(acc0[1][nt][0], acc0[1][nt][1], acc0[1][nt][2], acc0[1][nt][3],
                            X2.z, X3.z, X2.w, X3.w, Bv.z, Bv.w);
                    // acc1 = Y @ Wh (same Bv)
                    mma_f16(acc1[0][nt][0], acc1[0][nt][1], acc1[0][nt][2], acc1[0][nt][3],
                            Y0.x, Y1.x, Y0.y, Y1.y, Bv.x, Bv.y);
                    mma_f16(acc1[1][nt][0], acc1[1][nt][1], acc1[1][nt][2], acc1[1][nt][3],
                            Y2.x, Y3.x, Y2.y, Y3.y, Bv.x, Bv.y);
                    mma_f16(acc1[0][nt][0], acc1[0][nt][1], acc1[0][nt][2], acc1[0][nt][3],
                            Y0.z, Y1.z, Y0.w, Y1.w, Bv.z, Bv.w);
                    mma_f16(acc1[1][nt][0], acc1[1][nt][1], acc1[1][nt][2], acc1[1][nt][3],
                            Y2.z, Y3.z, Y2.w, Y3.w, Bv.z, Bv.w);
                    // accC = X @ Wx1
                    mma_f16(accC[0][nt][0], accC[0][nt][1], accC[0][nt][2], accC[0][nt][3],
                            X0.x, X1.x, X0.y, X1.y, Cv.x, Cv.y);
                    mma_f16(accC[1][nt][0], accC[1][nt][1], accC[1][nt][2], accC[1][nt][3],
                            X2.x, X3.x, X2.y, X3.y, Cv.x, Cv.y);
                    mma_f16(accC[0][nt][0], accC[0][nt][1], accC[0][nt][2], accC[0][nt][3],
                            X0.z, X1.z, X0.w, X1.w, Cv.z, Cv.w);
                    mma_f16(accC[1][nt][0], accC[1][nt][1], accC[1][nt][2], accC[1][nt][3],
                            X2.z, X3.z, X2.w, X3.w, Cv.z, Cv.w);
                }
                X0 = NX0; X1 = NX1; X2 = NX2; X3 = NX3;
                Y0 = NY0; Y1 = NY1; Y2 = NY2; Y3 = NY3;
            }

            // spill: acc0/acc1 fp32, accC fp16 carry for round s+1
            float*  P0s = Ps0 + ks * 64 * PS_STRIDE;
            float*  P1s = Ps1 + ks * 64 * PS_STRIDE;
            __half* PCs = PsC + ks * 64 * PS_STRIDE;
#pragma unroll
            for (int mt = 0; mt < 2; mt++) {
                const int r = wm * 32 + mt * 16 + grp;
#pragma unroll
                for (int nt = 0; nt < 4; nt++) {
                    const int c = nt * 8 + tg * 2;
                    *reinterpret_cast<float2*>(P0s + (r    ) * PS_STRIDE + c) =
                        make_float2(acc0[mt][nt][0], acc0[mt][nt][1]);
                    *reinterpret_cast<float2*>(P0s + (r + 8) * PS_STRIDE + c) =
                        make_float2(acc0[mt][nt][2], acc0[mt][nt][3]);
                    *reinterpret_cast<float2*>(P1s + (r    ) * PS_STRIDE + c) =
                        make_float2(acc1[mt][nt][0], acc1[mt][nt][1]);
                    *reinterpret_cast<float2*>(P1s + (r + 8) * PS_STRIDE + c) =
                        make_float2(acc1[mt][nt][2], acc1[mt][nt][3]);
                    *reinterpret_cast<__half2*>(PCs + (r    ) * PS_STRIDE + c) =
                        __floats2half2_rn(accC[mt][nt][0], accC[mt][nt][1]);
                    *reinterpret_cast<__half2*>(PCs + (r + 8) * PS_STRIDE + c) =
                        __floats2half2_rn(accC[mt][nt][2], accC[mt][nt][3]);
                }
            }
        }
        __syncthreads();

        // ---- epilogue rec0: h0(s) (critical-path store) ----
        if (s < SEQ) {
            __half* hw = h0buf[s % 3];
#pragma unroll
            for (int it = 0; it < 2; it++) {
                int idx = tid + it * NTHR;
                int b = idx >> 3, j = idx & 7;
                int col = j << 2;
                float4 p0 = *reinterpret_cast<const float4*>(Ps0 + 0 * 64 * PS_STRIDE + b * PS_STRIDE + col);
                float4 p1 = *reinterpret_cast<const float4*>(Ps0 + 1 * 64 * PS_STRIDE + b * PS_STRIDE + col);
                float4 p2 = *reinterpret_cast<const float4*>(Ps0 + 2 * 64 * PS_STRIDE + b * PS_STRIDE + col);
                float4 p3 = *reinterpret_cast<const float4*>(Ps0 + 3 * 64 * PS_STRIDE + b * PS_STRIDE + col);

                float pi  = xv[it].x + ((p0.x + p1.x) + (p2.x + p3.x));
                float pfv = xv[it].y + ((p0.y + p1.y) + (p2.y + p3.y));
                float pg  = xv[it].z + ((p0.z + p1.z) + (p2.z + p3.z));
                float po  = xv[it].w + ((p0.w + p1.w) + (p2.w + p3.w));

                float gi = sigmoidf_(pi);
                float gf = sigmoidf_(pfv);
                float gg = tanhfast(pg);
                float go = sigmoidf_(po);

                float cv = gf * c0reg[it] + gi * gg;
                c0reg[it] = cv;
                float hv = go * tanhfast(cv);
                hw[b * HDIM + hperm16(J0 + j)] = __float2half(hv);
            }
        }

        // ---- epilogue rec1: h1(s-2) (critical store); seq/cdump deferred ----
        float hv1[2]; float cv1[2];
        if (s >= 2) {
            __half* hw = h1buf[s & 1];
#pragma unroll
            for (int it = 0; it < 2; it++) {
                int idx = tid + it * NTHR;
                int b = idx >> 3, j = idx & 7;
                int col = j << 2;
                float4 p0 = *reinterpret_cast<const float4*>(Ps1 + 0 * 64 * PS_STRIDE + b * PS_STRIDE + col);
                float4 p1 = *reinterpret_cast<const float4*>(Ps1 + 1 * 64 * PS_STRIDE + b * PS_STRIDE + col);
                float4 p2 = *reinterpret_cast<const float4*>(Ps1 + 2 * 64 * PS_STRIDE + b * PS_STRIDE + col);
                float4 p3 = *reinterpret_cast<const float4*>(Ps1 + 3 * 64 * PS_STRIDE + b * PS_STRIDE + col);

                float pi  = bs1[it].x + rc[it].x + ((p0.x + p1.x) + (p2.x + p3.x));
                float pfv = bs1[it].y + rc[it].y + ((p0.y + p1.y) + (p2.y + p3.y));
                float pg  = bs1[it].z + rc[it].z + ((p0.z + p1.z) + (p2.z + p3.z));
                float po  = bs1[it].w + rc[it].w + ((p0.w + p1.w) + (p2.w + p3.w));

                float gi = sigmoidf_(pi);
                float gf = sigmoidf_(pfv);
                float gg = tanhfast(pg);
                float go = sigmoidf_(po);

                float cv = gf * c1reg[it] + gi * gg;
                c1reg[it] = cv;
                float hv = go * tanhfast(cv);
                cv1[it] = cv; hv1[it] = hv;

                int J = J0 + j;
                hw[b * HDIM + hperm16(J)] = __float2half(hv);
            }
        }

        __syncthreads();
        if (tid == 0) st_rel(&g_flags[blockIdx.x], base + 2 + (unsigned)s);

        // ---- deferred non-critical stores (after flag release, streaming) ----
        if (s >= 2) {
            float* so = seq_out + (size_t)(s - 2) * BS * HDIM;
#pragma unroll
            for (int it = 0; it < 2; it++) {
                int idx = tid + it * NTHR;
                int b = idx >> 3, j = idx & 7;
                int J = J0 + j;
                __stcs(so + (size_t)b * HDIM + J, hv1[it]);
                if (s == SEQ + 1) __stcs(cdump + b * HDIM + J, cv1[it]);
            }
        }
    }
}

// ---------------- tail: (h, c) after the sequence --------------------------------
__global__ void copy_tail(const float* __restrict__ hsrc, const float* __restrict__ csrc,
                          float* __restrict__ dst) {
    int i = blockIdx.x * blockDim.x + threadIdx.x;
    if (i < BS * HDIM) {
        dst[i] = hsrc[i];
        dst[BS * HDIM + i] = csrc[i];
    }
}

// ---------------- launcher --------------------------------------------------------
extern "C" void kernel_launch(void* const* d_in, const int* in_sizes, int n_in,
                              void* d_out, int out_size) {
    (void)in_sizes; (void)n_in;

    const float* x     = (const float*)d_in[0];
    const float* Wii0  = (const float*)d_in[1];
    const float* Wii   = (const float*)d_in[2];
    const float* Whi   = (const float*)d_in[3];
    const float* Wif0  = (const float*)d_in[4];
    const float* Wif   = (const float*)d_in[5];
    const float* Whf   = (const float*)d_in[6];
    const float* Wig0  = (const float*)d_in[7];
    const float* Wig   = (const float*)d_in[8];
    const float* Whg   = (const float*)d_in[9];
    const float* Wio0  = (const float*)d_in[10];
    const float* Wio   = (const float*)d_in[11];
    const float* Who   = (const float*)d_in[12];
    const float* bi    = (const float*)d_in[13];
    const float* bf    = (const float*)d_in[14];
    const float* bg    = (const float*)d_in[15];
    const float* bo    = (const float*)d_in[16];

    float *pBias, *pC;
    __half *pWx0h, *pWx1h, *pWhh, *pXw, *pAh, *pH0A, *pH0B, *pH0C, *pH1A, *pH1B;
    cudaGetSymbolAddress((void**)&pWx0h, g_Wx0h);
    cudaGetSymbolAddress((void**)&pWx1h, g_Wx1h);
    cudaGetSymbolAddress((void**)&pWhh,  g_Whh);
    cudaGetSymbolAddress((void**)&pBias, g_bias);
    cudaGetSymbolAddress((void**)&pXw,   g_xw);
    cudaGetSymbolAddress((void**)&pAh,   g_Ah);
    cudaGetSymbolAddress((void**)&pH0A,  g_h0A);
    cudaGetSymbolAddress((void**)&pH0B,  g_h0B);
    cudaGetSymbolAddress((void**)&pH0C,  g_h0C);
    cudaGetSymbolAddress((void**)&pH1A,  g_h1A);
    cudaGetSymbolAddress((void**)&pH1B,  g_h1B);
    cudaGetSymbolAddress((void**)&pC,    g_c);

    float* out = (float*)d_out;

    static bool attr_set = false;
    if (!attr_set) {
        cudaFuncSetAttribute(lstm_fused,
                             cudaFuncAttributeMaxDynamicSharedMemorySize, SMEM_BYTES);
        cudaFuncSetAttribute(gemm_xw_f16,
                             cudaFuncAttributeMaxDynamicSharedMemorySize, GEMM_SMEM);
        attr_set = true;
    }

    // launch order: pack_all, cvtA, gemm0, lstm_fused (4th = ncu-profiled)
    pack_all<<<3073, 256>>>(Wii0, Wif0, Wig0, Wio0,
                            Wii,  Wif,  Wig,  Wio,
                            Whi,  Whf,  Whg,  Who,
                            bi, bf, bg, bo,
                            pWx0h, pWx1h, pWhh, pBias);
    {
        int n = SEQ * BS * IN_DIM;
        cvtA<<<(n / 2 + 255) / 256, 256>>>(x, pAh, n);
    }

    const dim3 gemm_grid(G4 / 128, (SEQ * BS) / 128);  // (32, 256)
    gemm_xw_f16<<<gemm_grid, 256, GEMM_SMEM>>>(pAh, pWx0h, pXw, pBias);

    lstm_fused<<<NCTA, NTHR, SMEM_BYTES>>>(pXw, pH0A, pH0B, pH0C, pH1A, pH1B, pC, out);

    // tail: final (h, c) of layer 1. h final = seq output at t = SEQ-1.
    size_t seqN = (size_t)SEQ * BS * HDIM;
    if ((size_t)out_size >= seqN + 2 * (size_t)BS * HDIM) {
        copy_tail<<<(BS * HDIM + 255) / 256, 256>>>(out + seqN - (size_t)BS * HDIM,
                                                    pC, out + seqN);
    }
}